// round 3
// baseline (speedup 1.0000x reference)
#include <cuda_runtime.h>
#include <cstdint>

// ---------------------------------------------------------------------------
// Problem constants
// ---------------------------------------------------------------------------
constexpr int BB   = 8;
constexpr int HH   = 128;
constexpr int WW   = 128;
constexpr int CC   = 192;
constexpr int NHH  = 6;
constexpr int HDD  = 32;
constexpr int WS   = 8;
constexpr int SH   = 4;           // shift
constexpr int NT   = 64;          // tokens per window
constexpr int NWIN = 2048;        // B * 256 windows
constexpr int MROWS = 131072;     // total tokens
constexpr float SCALE_F = 0.17677669529663689f;  // 32^-0.5

// ---------------------------------------------------------------------------
// Scratch (static device globals; no runtime allocation).
// NOTE: these must ONLY be referenced from device code. Passing them as
// kernel arguments from host code passes the host shadow address (silently
// wrong on GB300 because ATS makes host addresses dereferenceable).
// ---------------------------------------------------------------------------
__device__ float g_hwin[(size_t)MROWS * CC];      // LN1 output, window-token order
__device__ float g_q[(size_t)NWIN * NHH * NT * HDD];
__device__ float g_k[(size_t)NWIN * NHH * NT * HDD];
__device__ float g_v[(size_t)NWIN * NHH * NT * HDD];
__device__ float g_att[(size_t)MROWS * CC];       // attention out, window-token order
__device__ float g_xmid[(size_t)MROWS * CC];      // x + attn branch, original order
__device__ float g_ln2[(size_t)MROWS * CC];
__device__ float g_h1[(size_t)MROWS * 4 * CC];    // fc1 output

// ---------------------------------------------------------------------------
// LayerNorm.
// LMODE 0: in = x (arg), gather through shift+window mapping -> g_hwin
// LMODE 1: in = g_xmid (device global), plain rows -> g_ln2
// One warp per token, 6 elements per lane.
// ---------------------------------------------------------------------------
template<int LMODE>
__global__ void ln_kernel(const float* __restrict__ xin,
                          const float* __restrict__ gam,
                          const float* __restrict__ bet)
{
    int warp = (blockIdx.x * blockDim.x + threadIdx.x) >> 5;
    int lane = threadIdx.x & 31;
    if (warp >= MROWS) return;

    const float* in = (LMODE == 0) ? xin : g_xmid;
    float* out      = (LMODE == 0) ? g_hwin : g_ln2;

    int src = warp;
    if (LMODE == 0) {
        int w = warp >> 6, t = warp & 63;
        int bb = w >> 8, wi = w & 255;
        int wy = wi >> 4, wx = wi & 15;
        int ty = t >> 3, tx = t & 7;
        int oy = (wy * 8 + ty + SH) & 127;
        int ox = (wx * 8 + tx + SH) & 127;
        src = (bb << 14) + (oy << 7) + ox;
    }
    const float* row = in + (size_t)src * CC;
    float v[6];
    float s = 0.f, s2 = 0.f;
#pragma unroll
    for (int i = 0; i < 6; i++) {
        v[i] = row[lane + 32 * i];
        s  += v[i];
        s2 += v[i] * v[i];
    }
#pragma unroll
    for (int off = 16; off; off >>= 1) {
        s  += __shfl_xor_sync(0xffffffffu, s,  off);
        s2 += __shfl_xor_sync(0xffffffffu, s2, off);
    }
    float mu  = s * (1.f / CC);
    float var = s2 * (1.f / CC) - mu * mu;
    float inv = rsqrtf(var + 1e-5f);
    float* orow = out + (size_t)warp * CC;
#pragma unroll
    for (int i = 0; i < 6; i++) {
        int c = lane + 32 * i;
        orow[c] = (v[i] - mu) * inv * gam[c] + bet[c];
    }
}

// ---------------------------------------------------------------------------
// Tiled SGEMM:  C[m][n] = sum_k A[m][k] * W[n][k] + bias[n]   (+ epilogue)
// 64x64 tile, BK=32, 256 threads, 4x4 micro-tile with x16 striding.
// MODE 0: A=g_hwin  -> QKV scatter into g_q/g_k/g_v (q scaled)
// MODE 1: A=g_ln2   -> leaky relu -> g_h1
// MODE 2: A=g_h1    -> + g_xmid -> Cext (d_out)
// MODE 3: A=g_att   -> window-reverse scatter, + Rext (x) -> g_xmid
// ---------------------------------------------------------------------------
template<int MODE, int KDIM, int NDIM>
__global__ void gemm_kernel(const float* __restrict__ Wt,
                            const float* __restrict__ bias,
                            const float* __restrict__ Rext,
                            float* __restrict__ Cext)
{
    constexpr int BK = 32;
    __shared__ float As[BK][65];
    __shared__ float Bs[BK][65];

    const float* A = (MODE == 0) ? g_hwin :
                     (MODE == 1) ? g_ln2  :
                     (MODE == 2) ? g_h1   : g_att;

    int m0 = blockIdx.y * 64;
    int n0 = blockIdx.x * 64;
    int tid = threadIdx.x;
    int tx = tid & 15, ty = tid >> 4;

    float acc[4][4] = {};

    for (int kt = 0; kt < KDIM; kt += BK) {
#pragma unroll
        for (int i = 0; i < 8; i++) {
            int idx = tid + i * 256;
            int r = idx >> 5, k = idx & 31;
            As[k][r] = A [(size_t)(m0 + r) * KDIM + kt + k];
            Bs[k][r] = Wt[(size_t)(n0 + r) * KDIM + kt + k];
        }
        __syncthreads();
#pragma unroll
        for (int k = 0; k < BK; k++) {
            float a[4], b[4];
#pragma unroll
            for (int i = 0; i < 4; i++) a[i] = As[k][ty + 16 * i];
#pragma unroll
            for (int j = 0; j < 4; j++) b[j] = Bs[k][tx + 16 * j];
#pragma unroll
            for (int i = 0; i < 4; i++)
#pragma unroll
                for (int j = 0; j < 4; j++)
                    acc[i][j] += a[i] * b[j];
        }
        __syncthreads();
    }

#pragma unroll
    for (int i = 0; i < 4; i++) {
        int m = m0 + ty + 16 * i;
#pragma unroll
        for (int j = 0; j < 4; j++) {
            int n = n0 + tx + 16 * j;
            float val = acc[i][j] + bias[n];
            if (MODE == 0) {
                int s   = n / 192;
                int rem = n % 192;
                int nh  = rem >> 5, d = rem & 31;
                int w = m >> 6, t = m & 63;
                size_t off = ((size_t)((w * NHH + nh) * NT + t)) * HDD + d;
                if      (s == 0) g_q[off] = val * SCALE_F;
                else if (s == 1) g_k[off] = val;
                else             g_v[off] = val;
            } else if (MODE == 1) {
                val = val > 0.f ? val : 0.2f * val;
                g_h1[(size_t)m * NDIM + n] = val;
            } else if (MODE == 2) {
                size_t o = (size_t)m * NDIM + n;
                Cext[o] = g_xmid[o] + val;          // residual from device global
            } else {
                int w = m >> 6, t = m & 63;
                int bb = w >> 8, wi = w & 255;
                int wy = wi >> 4, wx = wi & 15;
                int ty2 = t >> 3, tx2 = t & 7;
                int oy = (wy * 8 + ty2 + SH) & 127;
                int ox = (wx * 8 + tx2 + SH) & 127;
                size_t orow = ((size_t)bb << 14) + (oy << 7) + ox;
                size_t o = orow * NDIM + n;
                g_xmid[o] = Rext[o] + val;          // Rext = x (harness pointer)
            }
        }
    }
}

// ---------------------------------------------------------------------------
// Attention: one block per (window, head).  128 threads.
// S = Q K^T (Q pre-scaled) + rel-pos bias + shift mask; softmax; O = P V.
// ---------------------------------------------------------------------------
__global__ void attn_kernel(const float* __restrict__ rpb)
{
    int wh = blockIdx.x;             // 0 .. NWIN*NHH-1
    int w  = wh / NHH, nh = wh % NHH;
    int wi = w & 255;
    int wy = wi >> 4, wx = wi & 15;

    __shared__ float Qs[64][33];
    __shared__ float Ks[64][33];
    __shared__ float Vs[64][33];
    __shared__ float Ps[64][65];
    __shared__ int   lab[64];

    int tid = threadIdx.x;           // 128
    size_t base = (size_t)(w * NHH + nh) * NT * HDD;
#pragma unroll
    for (int it = 0; it < 16; it++) {
        int idx = tid + it * 128;
        int r = idx >> 5, d = idx & 31;
        Qs[r][d] = g_q[base + idx];
        Ks[r][d] = g_k[base + idx];
        Vs[r][d] = g_v[base + idx];
    }
    if (tid < 64) {
        int ty = tid >> 3, tx = tid & 7;
        int y = wy * 8 + ty, x = wx * 8 + tx;
        int ry = (y < HH - WS) ? 0 : ((y < HH - SH) ? 1 : 2);
        int rx = (x < WW - WS) ? 0 : ((x < WW - SH) ? 1 : 2);
        lab[tid] = ry * 3 + rx;
    }
    __syncthreads();

    int r = tid >> 1, half = tid & 1, c0 = half * 32;

    float qreg[32];
#pragma unroll
    for (int d = 0; d < 32; d++) qreg[d] = Qs[r][d];

    float sv[32];
    int labr = lab[r];
#pragma unroll
    for (int j = 0; j < 32; j++) {
        int c = c0 + j;
        float s = 0.f;
#pragma unroll
        for (int d = 0; d < 32; d++) s += qreg[d] * Ks[c][d];
        int dy = (r >> 3) - (c >> 3) + 7;
        int dx = (r & 7) - (c & 7) + 7;
        s += rpb[(dy * 15 + dx) * NHH + nh];
        if (labr != lab[c]) s -= 100.f;
        sv[j] = s;
    }
    float mx = sv[0];
#pragma unroll
    for (int j = 1; j < 32; j++) mx = fmaxf(mx, sv[j]);
    mx = fmaxf(mx, __shfl_xor_sync(0xffffffffu, mx, 1));
    float sum = 0.f;
#pragma unroll
    for (int j = 0; j < 32; j++) { sv[j] = __expf(sv[j] - mx); sum += sv[j]; }
    sum += __shfl_xor_sync(0xffffffffu, sum, 1);
    float inv = 1.f / sum;
#pragma unroll
    for (int j = 0; j < 32; j++) Ps[r][c0 + j] = sv[j] * inv;
    __syncthreads();

    float acc[16] = {};
    int d0 = half * 16;
    for (int mm = 0; mm < 64; mm++) {
        float p = Ps[r][mm];
#pragma unroll
        for (int j = 0; j < 16; j++) acc[j] += p * Vs[mm][d0 + j];
    }
    float* ob = g_att + (size_t)(w * NT + r) * CC + nh * HDD + d0;
#pragma unroll
    for (int j = 0; j < 16; j++) ob[j] = acc[j];
}

// ---------------------------------------------------------------------------
// Launch.  Only harness pointers cross the host/device boundary.
// ---------------------------------------------------------------------------
extern "C" void kernel_launch(void* const* d_in, const int* in_sizes, int n_in,
                              void* d_out, int out_size)
{
    const float* x       = (const float*)d_in[0];
    const float* norm1_g = (const float*)d_in[1];
    const float* norm1_b = (const float*)d_in[2];
    const float* qkv_w   = (const float*)d_in[3];
    const float* qkv_b   = (const float*)d_in[4];
    const float* proj_w  = (const float*)d_in[5];
    const float* proj_b  = (const float*)d_in[6];
    const float* rpb     = (const float*)d_in[7];
    const float* norm2_g = (const float*)d_in[8];
    const float* norm2_b = (const float*)d_in[9];
    const float* fc1_w   = (const float*)d_in[10];
    const float* fc1_b   = (const float*)d_in[11];
    const float* fc2_w   = (const float*)d_in[12];
    const float* fc2_b   = (const float*)d_in[13];
    float* out = (float*)d_out;

    // 1. LN1 + shift + window partition (gathered) -> g_hwin
    ln_kernel<0><<<MROWS / 8, 256>>>(x, norm1_g, norm1_b);

    // 2. QKV projection -> g_q/g_k/g_v
    gemm_kernel<0, 192, 576><<<dim3(9, 2048), 256>>>(qkv_w, qkv_b, nullptr, nullptr);

    // 3. Windowed attention -> g_att
    attn_kernel<<<NWIN * NHH, 128>>>(rpb);

    // 4. Output projection + window reverse + residual -> g_xmid
    gemm_kernel<3, 192, 192><<<dim3(3, 2048), 256>>>(proj_w, proj_b, x, nullptr);

    // 5. LN2 -> g_ln2
    ln_kernel<1><<<MROWS / 8, 256>>>(nullptr, norm2_g, norm2_b);

    // 6. FC1 + leaky relu -> g_h1
    gemm_kernel<1, 192, 768><<<dim3(12, 2048), 256>>>(fc1_w, fc1_b, nullptr, nullptr);

    // 7. FC2 + residual -> out
    gemm_kernel<2, 768, 192><<<dim3(3, 2048), 256>>>(fc2_w, fc2_b, nullptr, out);
}

// round 7
// speedup vs baseline: 2.7070x; 2.7070x over previous
#include <cuda_runtime.h>
#include <cuda_bf16.h>
#include <cstdint>

using bf16 = __nv_bfloat16;

// ---------------------------------------------------------------------------
// Problem constants
// ---------------------------------------------------------------------------
constexpr int HH   = 128;
constexpr int WW   = 128;
constexpr int CC   = 192;
constexpr int NHH  = 6;
constexpr int HDD  = 32;
constexpr int WS   = 8;
constexpr int SH   = 4;
constexpr int NT   = 64;
constexpr int NWIN = 2048;
constexpr int MROWS = 131072;
constexpr float SCALE_F = 0.17677669529663689f;

// ---------------------------------------------------------------------------
// Scratch (device globals only referenced from device code)
// ---------------------------------------------------------------------------
__device__ bf16  g_hwin[(size_t)MROWS * CC];        // LN1 out, window order (bf16)
__device__ float g_q[(size_t)NWIN * NHH * NT * HDD];
__device__ float g_k[(size_t)NWIN * NHH * NT * HDD];
__device__ float g_v[(size_t)NWIN * NHH * NT * HDD];
__device__ bf16  g_att[(size_t)MROWS * CC];         // attn out, window order (bf16)
__device__ float g_xmid[(size_t)MROWS * CC];        // x + attn branch (fp32)
__device__ bf16  g_ln2[(size_t)MROWS * CC];         // LN2 out (bf16)
__device__ bf16  g_h1[(size_t)MROWS * 4 * CC];      // fc1 out (bf16)
// bf16 weights
__device__ bf16  g_wqkv[576 * 192];
__device__ bf16  g_wproj[192 * 192];
__device__ bf16  g_wfc1[768 * 192];
__device__ bf16  g_wfc2[192 * 768];

// ---------------------------------------------------------------------------
// Weight conversion fp32 -> bf16 (one launch)
// ---------------------------------------------------------------------------
__global__ void cvt_weights(const float* __restrict__ qkv,
                            const float* __restrict__ proj,
                            const float* __restrict__ fc1,
                            const float* __restrict__ fc2)
{
    int i = blockIdx.x * blockDim.x + threadIdx.x;   // < 147456
    if (i < 576 * 192) g_wqkv[i]  = __float2bfloat16(qkv[i]);
    if (i < 192 * 192) g_wproj[i] = __float2bfloat16(proj[i]);
    if (i < 768 * 192) { g_wfc1[i] = __float2bfloat16(fc1[i]);
                         g_wfc2[i] = __float2bfloat16(fc2[i]); }
}

// ---------------------------------------------------------------------------
// LayerNorm.  LMODE 0: gather shift+window from x -> g_hwin (bf16)
//             LMODE 1: g_xmid -> g_ln2 (bf16)
// ---------------------------------------------------------------------------
template<int LMODE>
__global__ void ln_kernel(const float* __restrict__ xin,
                          const float* __restrict__ gam,
                          const float* __restrict__ bet)
{
    int warp = (blockIdx.x * blockDim.x + threadIdx.x) >> 5;
    int lane = threadIdx.x & 31;
    if (warp >= MROWS) return;

    const float* in = (LMODE == 0) ? xin : g_xmid;
    bf16* out       = (LMODE == 0) ? g_hwin : g_ln2;

    int src = warp;
    if (LMODE == 0) {
        int w = warp >> 6, t = warp & 63;
        int bb = w >> 8, wi = w & 255;
        int wy = wi >> 4, wx = wi & 15;
        int ty = t >> 3, tx = t & 7;
        int oy = (wy * 8 + ty + SH) & 127;
        int ox = (wx * 8 + tx + SH) & 127;
        src = (bb << 14) + (oy << 7) + ox;
    }
    const float* row = in + (size_t)src * CC;
    float v[6];
    float s = 0.f, s2 = 0.f;
#pragma unroll
    for (int i = 0; i < 6; i++) {
        v[i] = row[lane + 32 * i];
        s  += v[i];
        s2 += v[i] * v[i];
    }
#pragma unroll
    for (int off = 16; off; off >>= 1) {
        s  += __shfl_xor_sync(0xffffffffu, s,  off);
        s2 += __shfl_xor_sync(0xffffffffu, s2, off);
    }
    float mu  = s * (1.f / CC);
    float var = s2 * (1.f / CC) - mu * mu;
    float inv = rsqrtf(var + 1e-5f);
    bf16* orow = out + (size_t)warp * CC;
#pragma unroll
    for (int i = 0; i < 6; i++) {
        int c = lane + 32 * i;
        orow[c] = __float2bfloat16((v[i] - mu) * inv * gam[c] + bet[c]);
    }
}

// ---------------------------------------------------------------------------
// bf16 tensor-core GEMM:  C[m][n] = sum_k A[m][k]*W[n][k] + bias[n] (+epilogue)
// Block tile 128x64, BK=32, 256 threads (8 warps: 4 in M x 2 in N),
// each warp 32x32 via 2x4 m16n8k16 mma. fp32 accumulate.
// MODE 0: A=g_hwin,W=g_wqkv  -> QKV scatter fp32 (q scaled)
// MODE 1: A=g_ln2, W=g_wfc1  -> leaky relu -> g_h1 (bf16)
// MODE 2: A=g_h1,  W=g_wfc2  -> + g_xmid -> Cext (fp32 out)
// MODE 3: A=g_att, W=g_wproj -> window-reverse scatter, + x -> g_xmid
// ---------------------------------------------------------------------------
__device__ __forceinline__ void ldsm4(uint32_t* r, uint32_t a) {
    asm volatile("ldmatrix.sync.aligned.m8n8.x4.shared.b16 {%0,%1,%2,%3}, [%4];"
        : "=r"(r[0]), "=r"(r[1]), "=r"(r[2]), "=r"(r[3]) : "r"(a));
}
__device__ __forceinline__ void mma16816(float* c, const uint32_t* a, const uint32_t* b) {
    asm volatile("mma.sync.aligned.m16n8k16.row.col.f32.bf16.bf16.f32 "
        "{%0,%1,%2,%3}, {%4,%5,%6,%7}, {%8,%9}, {%0,%1,%2,%3};"
        : "+f"(c[0]), "+f"(c[1]), "+f"(c[2]), "+f"(c[3])
        : "r"(a[0]), "r"(a[1]), "r"(a[2]), "r"(a[3]), "r"(b[0]), "r"(b[1]));
}

template<int MODE, int KDIM, int NDIM>
__global__ void gemm_mma(const float* __restrict__ bias,
                         const float* __restrict__ Rext,
                         float* __restrict__ Cext)
{
    const bf16* A = (MODE == 0) ? g_hwin : (MODE == 1) ? g_ln2 :
                    (MODE == 2) ? g_h1   : g_att;
    const bf16* W = (MODE == 0) ? g_wqkv : (MODE == 1) ? g_wfc1 :
                    (MODE == 2) ? g_wfc2 : g_wproj;

    __shared__ __align__(16) bf16 As[128][40];
    __shared__ __align__(16) bf16 Ws[64][40];

    int m0 = blockIdx.y * 128, n0 = blockIdx.x * 64;
    int tid = threadIdx.x, lane = tid & 31, warp = tid >> 5;
    int wm = warp >> 1, wn = warp & 1;

    float acc[2][4][4] = {};

    for (int kt = 0; kt < KDIM; kt += 32) {
#pragma unroll
        for (int i = 0; i < 2; i++) {
            int idx = tid + i * 256;
            int r = idx >> 2, c8 = (idx & 3) * 8;
            *(uint4*)&As[r][c8] = *(const uint4*)&A[(size_t)(m0 + r) * KDIM + kt + c8];
        }
        {
            int r = tid >> 2, c8 = (tid & 3) * 8;
            *(uint4*)&Ws[r][c8] = *(const uint4*)&W[(size_t)(n0 + r) * KDIM + kt + c8];
        }
        __syncthreads();
#pragma unroll
        for (int ks = 0; ks < 2; ks++) {
            int kk = ks * 16;
            uint32_t afr[2][4];
#pragma unroll
            for (int mi = 0; mi < 2; mi++) {
                int row = wm * 32 + mi * 16 + (lane & 15);
                int col = kk + ((lane & 16) >> 1);
                ldsm4(afr[mi], (uint32_t)__cvta_generic_to_shared(&As[row][col]));
            }
            uint32_t bfr[4][2];
#pragma unroll
            for (int nh = 0; nh < 2; nh++) {
                int nb = wn * 32 + nh * 16;
                int row = nb + ((lane & 16) >> 1) + (lane & 7);
                int col = kk + (lane & 8);
                uint32_t t[4];
                ldsm4(t, (uint32_t)__cvta_generic_to_shared(&Ws[row][col]));
                bfr[2*nh  ][0] = t[0]; bfr[2*nh  ][1] = t[1];
                bfr[2*nh+1][0] = t[2]; bfr[2*nh+1][1] = t[3];
            }
#pragma unroll
            for (int mi = 0; mi < 2; mi++)
#pragma unroll
                for (int nj = 0; nj < 4; nj++)
                    mma16816(acc[mi][nj], afr[mi], bfr[nj]);
        }
        __syncthreads();
    }

    // epilogue: C[g / g+8][2t, 2t+1] per m16n8 tile
    int g = lane >> 2, t2 = (lane & 3) * 2;
#pragma unroll
    for (int mi = 0; mi < 2; mi++)
#pragma unroll
        for (int nj = 0; nj < 4; nj++)
#pragma unroll
            for (int e = 0; e < 4; e++) {
                int m = m0 + wm * 32 + mi * 16 + g + (e >> 1) * 8;
                int n = n0 + wn * 32 + nj * 8 + t2 + (e & 1);
                float val = acc[mi][nj][e] + bias[n];
                if (MODE == 0) {
                    int s   = n / 192;
                    int rem = n - s * 192;
                    int nh  = rem >> 5, d = rem & 31;
                    int w = m >> 6, t = m & 63;
                    size_t off = ((size_t)((w * NHH + nh) * NT + t)) * HDD + d;
                    if      (s == 0) g_q[off] = val * SCALE_F;
                    else if (s == 1) g_k[off] = val;
                    else             g_v[off] = val;
                } else if (MODE == 1) {
                    val = val > 0.f ? val : 0.2f * val;
                    g_h1[(size_t)m * NDIM + n] = __float2bfloat16(val);
                } else if (MODE == 2) {
                    size_t o = (size_t)m * NDIM + n;
                    Cext[o] = g_xmid[o] + val;
                } else {
                    int w = m >> 6, t = m & 63;
                    int bb = w >> 8, wi = w & 255;
                    int wy = wi >> 4, wx = wi & 15;
                    int ty2 = t >> 3, tx2 = t & 7;
                    int oy = (wy * 8 + ty2 + SH) & 127;
                    int ox = (wx * 8 + tx2 + SH) & 127;
                    size_t orow = ((size_t)bb << 14) + (oy << 7) + ox;
                    size_t o = orow * NDIM + n;
                    g_xmid[o] = Rext[o] + val;
                }
            }
}

// ---------------------------------------------------------------------------
// Attention: one block per (window, head).  fp32 math, bf16 output.
// ---------------------------------------------------------------------------
__global__ void attn_kernel(const float* __restrict__ rpb)
{
    int wh = blockIdx.x;
    int w  = wh / NHH, nh = wh - w * NHH;
    int wi = w & 255;
    int wy = wi >> 4, wx = wi & 15;

    __shared__ float Qs[64][33];
    __shared__ float Ks[64][33];
    __shared__ float Vs[64][33];
    __shared__ float Ps[64][65];
    __shared__ int   lab[64];

    int tid = threadIdx.x;
    size_t base = (size_t)(w * NHH + nh) * NT * HDD;
#pragma unroll
    for (int it = 0; it < 16; it++) {
        int idx = tid + it * 128;
        int r = idx >> 5, d = idx & 31;
        Qs[r][d] = g_q[base + idx];
        Ks[r][d] = g_k[base + idx];
        Vs[r][d] = g_v[base + idx];
    }
    if (tid < 64) {
        int ty = tid >> 3, tx = tid & 7;
        int y = wy * 8 + ty, x = wx * 8 + tx;
        int ry = (y < HH - WS) ? 0 : ((y < HH - SH) ? 1 : 2);
        int rx = (x < WW - WS) ? 0 : ((x < WW - SH) ? 1 : 2);
        lab[tid] = ry * 3 + rx;
    }
    __syncthreads();

    int r = tid >> 1, half = tid & 1, c0 = half * 32;

    float qreg[32];
#pragma unroll
    for (int d = 0; d < 32; d++) qreg[d] = Qs[r][d];

    float sv[32];
    int labr = lab[r];
#pragma unroll
    for (int j = 0; j < 32; j++) {
        int c = c0 + j;
        float s = 0.f;
#pragma unroll
        for (int d = 0; d < 32; d++) s += qreg[d] * Ks[c][d];
        int dy = (r >> 3) - (c >> 3) + 7;
        int dx = (r & 7) - (c & 7) + 7;
        s += rpb[(dy * 15 + dx) * NHH + nh];
        if (labr != lab[c]) s -= 100.f;
        sv[j] = s;
    }
    float mx = sv[0];
#pragma unroll
    for (int j = 1; j < 32; j++) mx = fmaxf(mx, sv[j]);
    mx = fmaxf(mx, __shfl_xor_sync(0xffffffffu, mx, 1));
    float sum = 0.f;
#pragma unroll
    for (int j = 0; j < 32; j++) { sv[j] = __expf(sv[j] - mx); sum += sv[j]; }
    sum += __shfl_xor_sync(0xffffffffu, sum, 1);
    float inv = 1.f / sum;
#pragma unroll
    for (int j = 0; j < 32; j++) Ps[r][c0 + j] = sv[j] * inv;
    __syncthreads();

    float acc[16] = {};
    int d0 = half * 16;
    for (int mm = 0; mm < 64; mm++) {
        float p = Ps[r][mm];
#pragma unroll
        for (int j = 0; j < 16; j++) acc[j] += p * Vs[mm][d0 + j];
    }
    bf16* ob = g_att + (size_t)(w * NT + r) * CC + nh * HDD + d0;
#pragma unroll
    for (int j = 0; j < 16; j++) ob[j] = __float2bfloat16(acc[j]);
}

// ---------------------------------------------------------------------------
// Launch
// ---------------------------------------------------------------------------
extern "C" void kernel_launch(void* const* d_in, const int* in_sizes, int n_in,
                              void* d_out, int out_size)
{
    const float* x       = (const float*)d_in[0];
    const float* norm1_g = (const float*)d_in[1];
    const float* norm1_b = (const float*)d_in[2];
    const float* qkv_w   = (const float*)d_in[3];
    const float* qkv_b   = (const float*)d_in[4];
    const float* proj_w  = (const float*)d_in[5];
    const float* proj_b  = (const float*)d_in[6];
    const float* rpb     = (const float*)d_in[7];
    const float* norm2_g = (const float*)d_in[8];
    const float* norm2_b = (const float*)d_in[9];
    const float* fc1_w   = (const float*)d_in[10];
    const float* fc1_b   = (const float*)d_in[11];
    const float* fc2_w   = (const float*)d_in[12];
    const float* fc2_b   = (const float*)d_in[13];
    float* out = (float*)d_out;

    // 0. weight conversion
    cvt_weights<<<576, 256>>>(qkv_w, proj_w, fc1_w, fc2_w);

    // 1. LN1 + shift + window partition -> g_hwin (bf16)
    ln_kernel<0><<<MROWS / 8, 256>>>(x, norm1_g, norm1_b);

    // 2. QKV projection -> g_q/g_k/g_v
    gemm_mma<0, 192, 576><<<dim3(9, 1024), 256>>>(qkv_b, nullptr, nullptr);

    // 3. Windowed attention -> g_att (bf16)
    attn_kernel<<<NWIN * NHH, 128>>>(rpb);

    // 4. Output projection + window reverse + residual -> g_xmid
    gemm_mma<3, 192, 192><<<dim3(3, 1024), 256>>>(proj_b, x, nullptr);

    // 5. LN2 -> g_ln2 (bf16)
    ln_kernel<1><<<MROWS / 8, 256>>>(nullptr, norm2_g, norm2_b);

    // 6. FC1 + leaky relu -> g_h1 (bf16)
    gemm_mma<1, 192, 768><<<dim3(12, 1024), 256>>>(fc1_b, nullptr, nullptr);

    // 7. FC2 + residual -> out
    gemm_mma<2, 768, 192><<<dim3(3, 1024), 256>>>(fc2_b, nullptr, out);
}

// round 8
// speedup vs baseline: 3.7952x; 1.4020x over previous
#include <cuda_runtime.h>
#include <cuda_bf16.h>
#include <cstdint>

using bf16 = __nv_bfloat16;

// ---------------------------------------------------------------------------
// Problem constants
// ---------------------------------------------------------------------------
constexpr int HH   = 128;
constexpr int WW   = 128;
constexpr int CC   = 192;
constexpr int NHH  = 6;
constexpr int HDD  = 32;
constexpr int WS   = 8;
constexpr int SH   = 4;
constexpr int NT   = 64;
constexpr int NWIN = 2048;
constexpr int MROWS = 131072;
constexpr float SCALE_F = 0.17677669529663689f;

// ---------------------------------------------------------------------------
// Scratch (device globals only referenced from device code)
// ---------------------------------------------------------------------------
__device__ bf16  g_hwin[(size_t)MROWS * CC];        // LN1 out, window order
__device__ bf16  g_qb[(size_t)NWIN * NHH * NT * HDD];  // q * scale, [wh][t][d]
__device__ bf16  g_kb[(size_t)NWIN * NHH * NT * HDD];  // k, [wh][t][d]
__device__ bf16  g_vt[(size_t)NWIN * NHH * NT * HDD];  // v transposed, [wh][d][t]
__device__ bf16  g_att[(size_t)MROWS * CC];         // attn out, window order
__device__ float g_xmid[(size_t)MROWS * CC];        // x + attn branch (fp32)
__device__ bf16  g_ln2[(size_t)MROWS * CC];
__device__ bf16  g_h1[(size_t)MROWS * 4 * CC];
__device__ float g_bias[NHH * NT * NT];             // rel-pos bias, [nh][r][c]
// bf16 weights
__device__ bf16  g_wqkv[576 * 192];
__device__ bf16  g_wproj[192 * 192];
__device__ bf16  g_wfc1[768 * 192];
__device__ bf16  g_wfc2[192 * 768];

// ---------------------------------------------------------------------------
// Weight conversion fp32 -> bf16
// ---------------------------------------------------------------------------
__global__ void cvt_weights(const float* __restrict__ qkv,
                            const float* __restrict__ proj,
                            const float* __restrict__ fc1,
                            const float* __restrict__ fc2)
{
    int i = blockIdx.x * blockDim.x + threadIdx.x;
    if (i < 576 * 192) g_wqkv[i]  = __float2bfloat16(qkv[i]);
    if (i < 192 * 192) g_wproj[i] = __float2bfloat16(proj[i]);
    if (i < 768 * 192) { g_wfc1[i] = __float2bfloat16(fc1[i]);
                         g_wfc2[i] = __float2bfloat16(fc2[i]); }
}

// ---------------------------------------------------------------------------
// Precompute relative-position bias table per head: g_bias[nh][r][c]
// ---------------------------------------------------------------------------
__global__ void bias_kernel(const float* __restrict__ rpb)
{
    int i = blockIdx.x * blockDim.x + threadIdx.x;
    if (i >= NHH * NT * NT) return;
    int nh = i >> 12, rc = i & 4095, r = rc >> 6, c = rc & 63;
    int dy = (r >> 3) - (c >> 3) + 7;
    int dx = (r & 7) - (c & 7) + 7;
    g_bias[i] = rpb[(dy * 15 + dx) * NHH + nh];
}

// ---------------------------------------------------------------------------
// LayerNorm.  LMODE 0: gather shift+window from x -> g_hwin (bf16)
//             LMODE 1: g_xmid -> g_ln2 (bf16)
// ---------------------------------------------------------------------------
template<int LMODE>
__global__ void ln_kernel(const float* __restrict__ xin,
                          const float* __restrict__ gam,
                          const float* __restrict__ bet)
{
    int warp = (blockIdx.x * blockDim.x + threadIdx.x) >> 5;
    int lane = threadIdx.x & 31;
    if (warp >= MROWS) return;

    const float* in = (LMODE == 0) ? xin : g_xmid;
    bf16* out       = (LMODE == 0) ? g_hwin : g_ln2;

    int src = warp;
    if (LMODE == 0) {
        int w = warp >> 6, t = warp & 63;
        int bb = w >> 8, wi = w & 255;
        int wy = wi >> 4, wx = wi & 15;
        int ty = t >> 3, tx = t & 7;
        int oy = (wy * 8 + ty + SH) & 127;
        int ox = (wx * 8 + tx + SH) & 127;
        src = (bb << 14) + (oy << 7) + ox;
    }
    const float* row = in + (size_t)src * CC;
    float v[6];
    float s = 0.f, s2 = 0.f;
#pragma unroll
    for (int i = 0; i < 6; i++) {
        v[i] = row[lane + 32 * i];
        s  += v[i];
        s2 += v[i] * v[i];
    }
#pragma unroll
    for (int off = 16; off; off >>= 1) {
        s  += __shfl_xor_sync(0xffffffffu, s,  off);
        s2 += __shfl_xor_sync(0xffffffffu, s2, off);
    }
    float mu  = s * (1.f / CC);
    float var = s2 * (1.f / CC) - mu * mu;
    float inv = rsqrtf(var + 1e-5f);
    bf16* orow = out + (size_t)warp * CC;
#pragma unroll
    for (int i = 0; i < 6; i++) {
        int c = lane + 32 * i;
        orow[c] = __float2bfloat16((v[i] - mu) * inv * gam[c] + bet[c]);
    }
}

// ---------------------------------------------------------------------------
// MMA helpers
// ---------------------------------------------------------------------------
__device__ __forceinline__ void ldsm4(uint32_t* r, uint32_t a) {
    asm volatile("ldmatrix.sync.aligned.m8n8.x4.shared.b16 {%0,%1,%2,%3}, [%4];"
        : "=r"(r[0]), "=r"(r[1]), "=r"(r[2]), "=r"(r[3]) : "r"(a));
}
__device__ __forceinline__ void mma16816(float* c, const uint32_t* a, const uint32_t* b) {
    asm volatile("mma.sync.aligned.m16n8k16.row.col.f32.bf16.bf16.f32 "
        "{%0,%1,%2,%3}, {%4,%5,%6,%7}, {%8,%9}, {%0,%1,%2,%3};"
        : "+f"(c[0]), "+f"(c[1]), "+f"(c[2]), "+f"(c[3])
        : "r"(a[0]), "r"(a[1]), "r"(a[2]), "r"(a[3]), "r"(b[0]), "r"(b[1]));
}
__device__ __forceinline__ uint32_t packbf(float a, float b) {
    __nv_bfloat162 h = __float22bfloat162_rn(make_float2(a, b));
    return *(uint32_t*)&h;
}

// ---------------------------------------------------------------------------
// bf16 tensor-core GEMM (same proven structure as R7)
// MODE 0: A=g_hwin,W=g_wqkv  -> bf16 q(scaled)/k/[vT] scatter
// MODE 1: A=g_ln2, W=g_wfc1  -> leaky relu -> g_h1 (bf16)
// MODE 2: A=g_h1,  W=g_wfc2  -> + g_xmid -> Cext (fp32 out)
// MODE 3: A=g_att, W=g_wproj -> window-reverse scatter, + x -> g_xmid
// ---------------------------------------------------------------------------
template<int MODE, int KDIM, int NDIM>
__global__ void gemm_mma(const float* __restrict__ bias,
                         const float* __restrict__ Rext,
                         float* __restrict__ Cext)
{
    const bf16* A = (MODE == 0) ? g_hwin : (MODE == 1) ? g_ln2 :
                    (MODE == 2) ? g_h1   : g_att;
    const bf16* W = (MODE == 0) ? g_wqkv : (MODE == 1) ? g_wfc1 :
                    (MODE == 2) ? g_wfc2 : g_wproj;

    __shared__ __align__(16) bf16 As[128][40];
    __shared__ __align__(16) bf16 Ws[64][40];

    int m0 = blockIdx.y * 128, n0 = blockIdx.x * 64;
    int tid = threadIdx.x, lane = tid & 31, warp = tid >> 5;
    int wm = warp >> 1, wn = warp & 1;

    float acc[2][4][4] = {};

    for (int kt = 0; kt < KDIM; kt += 32) {
#pragma unroll
        for (int i = 0; i < 2; i++) {
            int idx = tid + i * 256;
            int r = idx >> 2, c8 = (idx & 3) * 8;
            *(uint4*)&As[r][c8] = *(const uint4*)&A[(size_t)(m0 + r) * KDIM + kt + c8];
        }
        {
            int r = tid >> 2, c8 = (tid & 3) * 8;
            *(uint4*)&Ws[r][c8] = *(const uint4*)&W[(size_t)(n0 + r) * KDIM + kt + c8];
        }
        __syncthreads();
#pragma unroll
        for (int ks = 0; ks < 2; ks++) {
            int kk = ks * 16;
            uint32_t afr[2][4];
#pragma unroll
            for (int mi = 0; mi < 2; mi++) {
                int row = wm * 32 + mi * 16 + (lane & 15);
                int col = kk + ((lane & 16) >> 1);
                ldsm4(afr[mi], (uint32_t)__cvta_generic_to_shared(&As[row][col]));
            }
            uint32_t bfr[4][2];
#pragma unroll
            for (int nh = 0; nh < 2; nh++) {
                int nb = wn * 32 + nh * 16;
                int row = nb + ((lane & 16) >> 1) + (lane & 7);
                int col = kk + (lane & 8);
                uint32_t t[4];
                ldsm4(t, (uint32_t)__cvta_generic_to_shared(&Ws[row][col]));
                bfr[2*nh  ][0] = t[0]; bfr[2*nh  ][1] = t[1];
                bfr[2*nh+1][0] = t[2]; bfr[2*nh+1][1] = t[3];
            }
#pragma unroll
            for (int mi = 0; mi < 2; mi++)
#pragma unroll
                for (int nj = 0; nj < 4; nj++)
                    mma16816(acc[mi][nj], afr[mi], bfr[nj]);
        }
        __syncthreads();
    }

    int g = lane >> 2, t2 = (lane & 3) * 2;
#pragma unroll
    for (int mi = 0; mi < 2; mi++)
#pragma unroll
        for (int nj = 0; nj < 4; nj++)
#pragma unroll
            for (int e = 0; e < 4; e++) {
                int m = m0 + wm * 32 + mi * 16 + g + (e >> 1) * 8;
                int n = n0 + wn * 32 + nj * 8 + t2 + (e & 1);
                float val = acc[mi][nj][e] + bias[n];
                if (MODE == 0) {
                    int s   = n / 192;
                    int rem = n - s * 192;
                    int nh  = rem >> 5, d = rem & 31;
                    int w = m >> 6, t = m & 63;
                    size_t wh = (size_t)(w * NHH + nh);
                    if (s == 0)      g_qb[(wh * NT + t) * HDD + d] = __float2bfloat16(val * SCALE_F);
                    else if (s == 1) g_kb[(wh * NT + t) * HDD + d] = __float2bfloat16(val);
                    else             g_vt[(wh * HDD + d) * NT + t] = __float2bfloat16(val);
                } else if (MODE == 1) {
                    val = val > 0.f ? val : 0.2f * val;
                    g_h1[(size_t)m * NDIM + n] = __float2bfloat16(val);
                } else if (MODE == 2) {
                    size_t o = (size_t)m * NDIM + n;
                    Cext[o] = g_xmid[o] + val;
                } else {
                    int w = m >> 6, t = m & 63;
                    int bb = w >> 8, wi = w & 255;
                    int wy = wi >> 4, wx = wi & 15;
                    int ty2 = t >> 3, tx2 = t & 7;
                    int oy = (wy * 8 + ty2 + SH) & 127;
                    int ox = (wx * 8 + tx2 + SH) & 127;
                    size_t orow = ((size_t)bb << 14) + (oy << 7) + ox;
                    size_t o = orow * NDIM + n;
                    g_xmid[o] = Rext[o] + val;
                }
            }
}

// ---------------------------------------------------------------------------
// Tensor-core attention: one block per (window, head), 4 warps.
// Warp w computes rows [16w, 16w+16).  S = QK^T via mma, fp32 softmax in
// registers, P fragments re-sliced from S accumulators, PV via mma.
// ---------------------------------------------------------------------------
__global__ void attn_mma()
{
    int wh = blockIdx.x;
    int w  = wh / NHH;
    int wi = w & 255;
    int wy = wi >> 4, wx = wi & 15;
    int nh = wh - w * NHH;

    __shared__ __align__(16) bf16 Qs[64][40];
    __shared__ __align__(16) bf16 Ks[64][40];
    __shared__ __align__(16) bf16 Vt[32][72];
    __shared__ int lab[64];

    int tid = threadIdx.x, lane = tid & 31, warp = tid >> 5;
    size_t base = (size_t)wh * NT * HDD;

#pragma unroll
    for (int i = 0; i < 2; i++) {
        int idx = tid + i * 128;               // 256 uint4 per tensor
        int r = idx >> 2, c8 = (idx & 3) * 8;
        *(uint4*)&Qs[r][c8] = *(const uint4*)&g_qb[base + r * HDD + c8];
        *(uint4*)&Ks[r][c8] = *(const uint4*)&g_kb[base + r * HDD + c8];
        int rv = idx >> 3, cv = (idx & 7) * 8;
        *(uint4*)&Vt[rv][cv] = *(const uint4*)&g_vt[base + rv * NT + cv];
    }
    if (tid < 64) {
        int ty = tid >> 3, tx = tid & 7;
        int y = wy * 8 + ty, x = wx * 8 + tx;
        int ry = (y < HH - WS) ? 0 : ((y < HH - SH) ? 1 : 2);
        int rx = (x < WW - WS) ? 0 : ((x < WW - SH) ? 1 : 2);
        lab[tid] = ry * 3 + rx;
    }
    __syncthreads();

    int mrow = warp * 16;

    // ---- S = Q K^T ----
    uint32_t aq[2][4];
#pragma unroll
    for (int kc = 0; kc < 2; kc++)
        ldsm4(aq[kc], (uint32_t)__cvta_generic_to_shared(
            &Qs[mrow + (lane & 15)][kc * 16 + ((lane & 16) >> 1)]));

    float sacc[8][4] = {};
#pragma unroll
    for (int kc = 0; kc < 2; kc++)
#pragma unroll
        for (int p = 0; p < 4; p++) {
            uint32_t t4[4];
            ldsm4(t4, (uint32_t)__cvta_generic_to_shared(
                &Ks[p * 16 + ((lane & 16) >> 1) + (lane & 7)][kc * 16 + (lane & 8)]));
            mma16816(sacc[2 * p],     aq[kc], t4);
            mma16816(sacc[2 * p + 1], aq[kc], t4 + 2);
        }

    // ---- bias + mask + softmax (rows r0, r1 per lane) ----
    int g = lane >> 2, tq = lane & 3;
    int r0 = mrow + g, r1 = r0 + 8;
    const float2* b0 = (const float2*)&g_bias[(nh * NT + r0) * NT];
    const float2* b1 = (const float2*)&g_bias[(nh * NT + r1) * NT];
    int l0 = lab[r0], l1 = lab[r1];
    float mx0 = -1e30f, mx1 = -1e30f;
#pragma unroll
    for (int j = 0; j < 8; j++) {
        int c0 = 8 * j + 2 * tq;
        float2 bb0 = b0[4 * j + tq];
        float2 bb1 = b1[4 * j + tq];
        int lc0 = lab[c0], lc1 = lab[c0 + 1];
        sacc[j][0] += bb0.x + (l0 != lc0 ? -100.f : 0.f);
        sacc[j][1] += bb0.y + (l0 != lc1 ? -100.f : 0.f);
        sacc[j][2] += bb1.x + (l1 != lc0 ? -100.f : 0.f);
        sacc[j][3] += bb1.y + (l1 != lc1 ? -100.f : 0.f);
        mx0 = fmaxf(mx0, fmaxf(sacc[j][0], sacc[j][1]));
        mx1 = fmaxf(mx1, fmaxf(sacc[j][2], sacc[j][3]));
    }
    mx0 = fmaxf(mx0, __shfl_xor_sync(0xffffffffu, mx0, 1));
    mx0 = fmaxf(mx0, __shfl_xor_sync(0xffffffffu, mx0, 2));
    mx1 = fmaxf(mx1, __shfl_xor_sync(0xffffffffu, mx1, 1));
    mx1 = fmaxf(mx1, __shfl_xor_sync(0xffffffffu, mx1, 2));
    float s0 = 0.f, s1 = 0.f;
#pragma unroll
    for (int j = 0; j < 8; j++) {
        sacc[j][0] = __expf(sacc[j][0] - mx0);
        sacc[j][1] = __expf(sacc[j][1] - mx0);
        sacc[j][2] = __expf(sacc[j][2] - mx1);
        sacc[j][3] = __expf(sacc[j][3] - mx1);
        s0 += sacc[j][0] + sacc[j][1];
        s1 += sacc[j][2] + sacc[j][3];
    }
    s0 += __shfl_xor_sync(0xffffffffu, s0, 1);
    s0 += __shfl_xor_sync(0xffffffffu, s0, 2);
    s1 += __shfl_xor_sync(0xffffffffu, s1, 1);
    s1 += __shfl_xor_sync(0xffffffffu, s1, 2);
    float inv0 = 1.f / s0, inv1 = 1.f / s1;

    // ---- O = P V ----
    float oacc[4][4] = {};
#pragma unroll
    for (int kc = 0; kc < 4; kc++) {
        uint32_t pa[4];
        pa[0] = packbf(sacc[2*kc  ][0] * inv0, sacc[2*kc  ][1] * inv0);
        pa[1] = packbf(sacc[2*kc  ][2] * inv1, sacc[2*kc  ][3] * inv1);
        pa[2] = packbf(sacc[2*kc+1][0] * inv0, sacc[2*kc+1][1] * inv0);
        pa[3] = packbf(sacc[2*kc+1][2] * inv1, sacc[2*kc+1][3] * inv1);
#pragma unroll
        for (int p = 0; p < 2; p++) {
            uint32_t t4[4];
            ldsm4(t4, (uint32_t)__cvta_generic_to_shared(
                &Vt[p * 16 + ((lane & 16) >> 1) + (lane & 7)][kc * 16 + (lane & 8)]));
            mma16816(oacc[2 * p],     pa, t4);
            mma16816(oacc[2 * p + 1], pa, t4 + 2);
        }
    }

    // ---- write O (bf16, window-token order rows, head-sliced cols) ----
#pragma unroll
    for (int nj = 0; nj < 4; nj++) {
        int d = nh * HDD + 8 * nj + 2 * tq;
        __nv_bfloat162 v0 = __float22bfloat162_rn(make_float2(oacc[nj][0], oacc[nj][1]));
        __nv_bfloat162 v1 = __float22bfloat162_rn(make_float2(oacc[nj][2], oacc[nj][3]));
        *(__nv_bfloat162*)&g_att[(size_t)(w * NT + r0) * CC + d] = v0;
        *(__nv_bfloat162*)&g_att[(size_t)(w * NT + r1) * CC + d] = v1;
    }
}

// ---------------------------------------------------------------------------
// Launch
// ---------------------------------------------------------------------------
extern "C" void kernel_launch(void* const* d_in, const int* in_sizes, int n_in,
                              void* d_out, int out_size)
{
    const float* x       = (const float*)d_in[0];
    const float* norm1_g = (const float*)d_in[1];
    const float* norm1_b = (const float*)d_in[2];
    const float* qkv_w   = (const float*)d_in[3];
    const float* qkv_b   = (const float*)d_in[4];
    const float* proj_w  = (const float*)d_in[5];
    const float* proj_b  = (const float*)d_in[6];
    const float* rpb     = (const float*)d_in[7];
    const float* norm2_g = (const float*)d_in[8];
    const float* norm2_b = (const float*)d_in[9];
    const float* fc1_w   = (const float*)d_in[10];
    const float* fc1_b   = (const float*)d_in[11];
    const float* fc2_w   = (const float*)d_in[12];
    const float* fc2_b   = (const float*)d_in[13];
    float* out = (float*)d_out;

    cvt_weights<<<576, 256>>>(qkv_w, proj_w, fc1_w, fc2_w);
    bias_kernel<<<96, 256>>>(rpb);

    ln_kernel<0><<<MROWS / 8, 256>>>(x, norm1_g, norm1_b);

    gemm_mma<0, 192, 576><<<dim3(9, 1024), 256>>>(qkv_b, nullptr, nullptr);

    attn_mma<<<NWIN * NHH, 128>>>();

    gemm_mma<3, 192, 192><<<dim3(3, 1024), 256>>>(proj_b, x, nullptr);

    ln_kernel<1><<<MROWS / 8, 256>>>(nullptr, norm2_g, norm2_b);

    gemm_mma<1, 192, 768><<<dim3(12, 1024), 256>>>(fc1_b, nullptr, nullptr);

    gemm_mma<2, 768, 192><<<dim3(3, 1024), 256>>>(fc2_b, nullptr, out);
}

// round 10
// speedup vs baseline: 4.3042x; 1.1341x over previous
#include <cuda_runtime.h>
#include <cuda_bf16.h>
#include <cstdint>

using bf16 = __nv_bfloat16;

// ---------------------------------------------------------------------------
// Problem constants
// ---------------------------------------------------------------------------
constexpr int HH   = 128;
constexpr int WW   = 128;
constexpr int CC   = 192;
constexpr int NHH  = 6;
constexpr int HDD  = 32;
constexpr int WS   = 8;
constexpr int SH   = 4;
constexpr int NT   = 64;
constexpr int NWIN = 2048;
constexpr int MROWS = 131072;
constexpr float SCALE_F = 0.17677669529663689f;

// ---------------------------------------------------------------------------
// Scratch (device globals, only referenced from device code)
// ---------------------------------------------------------------------------
__device__ bf16  g_hwin[(size_t)MROWS * CC];
__device__ bf16  g_qb[(size_t)NWIN * NHH * NT * HDD];  // q*scale [wh][t][d]
__device__ bf16  g_kb[(size_t)NWIN * NHH * NT * HDD];  // k       [wh][t][d]
__device__ bf16  g_vt[(size_t)NWIN * NHH * NT * HDD];  // v^T     [wh][d][t]
__device__ bf16  g_att[(size_t)MROWS * CC];
__device__ float g_xmid[(size_t)MROWS * CC];
__device__ bf16  g_ln2[(size_t)MROWS * CC];
__device__ bf16  g_h1[(size_t)MROWS * 4 * CC];
__device__ float g_bias[NHH * NT * NT];
__device__ bf16  g_wqkv[576 * 192];
__device__ bf16  g_wproj[192 * 192];
__device__ bf16  g_wfc1[768 * 192];
__device__ bf16  g_wfc2[192 * 768];

// ---------------------------------------------------------------------------
// Helpers
// ---------------------------------------------------------------------------
__device__ __forceinline__ uint32_t smem_u32(const void* p) {
    return (uint32_t)__cvta_generic_to_shared(p);
}
__device__ __forceinline__ void cpasync16(uint32_t s, const void* g) {
    asm volatile("cp.async.cg.shared.global [%0], [%1], 16;" :: "r"(s), "l"(g));
}
__device__ __forceinline__ void ldsm4(uint32_t* r, uint32_t a) {
    asm volatile("ldmatrix.sync.aligned.m8n8.x4.shared.b16 {%0,%1,%2,%3}, [%4];"
        : "=r"(r[0]), "=r"(r[1]), "=r"(r[2]), "=r"(r[3]) : "r"(a));
}
__device__ __forceinline__ void mma16816(float* c, const uint32_t* a, const uint32_t* b) {
    asm volatile("mma.sync.aligned.m16n8k16.row.col.f32.bf16.bf16.f32 "
        "{%0,%1,%2,%3}, {%4,%5,%6,%7}, {%8,%9}, {%0,%1,%2,%3};"
        : "+f"(c[0]), "+f"(c[1]), "+f"(c[2]), "+f"(c[3])
        : "r"(a[0]), "r"(a[1]), "r"(a[2]), "r"(a[3]), "r"(b[0]), "r"(b[1]));
}
__device__ __forceinline__ uint32_t packbf(float a, float b) {
    __nv_bfloat162 h = __float22bfloat162_rn(make_float2(a, b));
    return *(uint32_t*)&h;
}

// ---------------------------------------------------------------------------
// Weight conversion fp32 -> bf16
// ---------------------------------------------------------------------------
__global__ void cvt_weights(const float* __restrict__ qkv,
                            const float* __restrict__ proj,
                            const float* __restrict__ fc1,
                            const float* __restrict__ fc2)
{
    int i = blockIdx.x * blockDim.x + threadIdx.x;
    if (i < 576 * 192) g_wqkv[i]  = __float2bfloat16(qkv[i]);
    if (i < 192 * 192) g_wproj[i] = __float2bfloat16(proj[i]);
    if (i < 768 * 192) { g_wfc1[i] = __float2bfloat16(fc1[i]);
                         g_wfc2[i] = __float2bfloat16(fc2[i]); }
}

// ---------------------------------------------------------------------------
// Precompute rel-pos bias table: g_bias[nh][r][c]
// ---------------------------------------------------------------------------
__global__ void bias_kernel(const float* __restrict__ rpb)
{
    int i = blockIdx.x * blockDim.x + threadIdx.x;
    if (i >= NHH * NT * NT) return;
    int nh = i >> 12, rc = i & 4095, r = rc >> 6, c = rc & 63;
    int dy = (r >> 3) - (c >> 3) + 7;
    int dx = (r & 7) - (c & 7) + 7;
    g_bias[i] = rpb[(dy * 15 + dx) * NHH + nh];
}

// ---------------------------------------------------------------------------
// LayerNorm (proven)
// ---------------------------------------------------------------------------
template<int LMODE>
__global__ void ln_kernel(const float* __restrict__ xin,
                          const float* __restrict__ gam,
                          const float* __restrict__ bet)
{
    int warp = (blockIdx.x * blockDim.x + threadIdx.x) >> 5;
    int lane = threadIdx.x & 31;
    if (warp >= MROWS) return;

    const float* in = (LMODE == 0) ? xin : g_xmid;
    bf16* out       = (LMODE == 0) ? g_hwin : g_ln2;

    int src = warp;
    if (LMODE == 0) {
        int w = warp >> 6, t = warp & 63;
        int bb = w >> 8, wi = w & 255;
        int wy = wi >> 4, wx = wi & 15;
        int ty = t >> 3, tx = t & 7;
        int oy = (wy * 8 + ty + SH) & 127;
        int ox = (wx * 8 + tx + SH) & 127;
        src = (bb << 14) + (oy << 7) + ox;
    }
    const float* row = in + (size_t)src * CC;
    float v[6];
    float s = 0.f, s2 = 0.f;
#pragma unroll
    for (int i = 0; i < 6; i++) {
        v[i] = row[lane + 32 * i];
        s  += v[i];
        s2 += v[i] * v[i];
    }
#pragma unroll
    for (int off = 16; off; off >>= 1) {
        s  += __shfl_xor_sync(0xffffffffu, s,  off);
        s2 += __shfl_xor_sync(0xffffffffu, s2, off);
    }
    float mu  = s * (1.f / CC);
    float var = s2 * (1.f / CC) - mu * mu;
    float inv = rsqrtf(var + 1e-5f);
    bf16* orow = out + (size_t)warp * CC;
#pragma unroll
    for (int i = 0; i < 6; i++) {
        int c = lane + 32 * i;
        orow[c] = __float2bfloat16((v[i] - mu) * inv * gam[c] + bet[c]);
    }
}

// ---------------------------------------------------------------------------
// HMMA GEMM, double-buffered cp.async pipeline.
// Block 128x64, BK=32, 128 threads = 4 warps, each warp a 32x64 tile
// (2 m16 x 8 n8 mma per k16 -> 16 mma per 6 ldmatrix).
// MODE 0: A=g_hwin,W=g_wqkv  -> q(scaled)/k/vT scatter (bf16)
// MODE 1: A=g_ln2, W=g_wfc1  -> leaky relu -> g_h1 (bf16)
// MODE 2: A=g_h1,  W=g_wfc2  -> + g_xmid -> Cext (fp32)
// MODE 3: A=g_att, W=g_wproj -> window-reverse scatter, + x -> g_xmid
// ---------------------------------------------------------------------------
template<int MODE, int KDIM, int NDIM>
__global__ void __launch_bounds__(128) gemm_mma(const float* __restrict__ bias,
                                                const float* __restrict__ Rext,
                                                float* __restrict__ Cext)
{
    const bf16* A = (MODE == 0) ? g_hwin : (MODE == 1) ? g_ln2 :
                    (MODE == 2) ? g_h1   : g_att;
    const bf16* W = (MODE == 0) ? g_wqkv : (MODE == 1) ? g_wfc1 :
                    (MODE == 2) ? g_wfc2 : g_wproj;

    __shared__ __align__(16) bf16 As[2][128][40];
    __shared__ __align__(16) bf16 Bs[2][64][40];

    int m0 = blockIdx.y * 128, n0 = blockIdx.x * 64;
    int tid = threadIdx.x, lane = tid & 31, warp = tid >> 5;

    constexpr int NCH = KDIM / 32;

    // prefetch lambda (cp.async, 16B each)
    auto prefetch = [&](int ch, int buf) {
        int kt = ch * 32;
#pragma unroll
        for (int i = 0; i < 4; i++) {
            int idx = tid + i * 128;
            int r = idx >> 2, c8 = (idx & 3) * 8;
            cpasync16(smem_u32(&As[buf][r][c8]),
                      &A[(size_t)(m0 + r) * KDIM + kt + c8]);
        }
#pragma unroll
        for (int i = 0; i < 2; i++) {
            int idx = tid + i * 128;
            int r = idx >> 2, c8 = (idx & 3) * 8;
            cpasync16(smem_u32(&Bs[buf][r][c8]),
                      &W[(size_t)(n0 + r) * KDIM + kt + c8]);
        }
    };

    float acc[2][8][4] = {};

    prefetch(0, 0);
    asm volatile("cp.async.commit_group;");

    for (int ch = 0; ch < NCH; ch++) {
        int buf = ch & 1;
        if (ch + 1 < NCH) {
            prefetch(ch + 1, buf ^ 1);
            asm volatile("cp.async.commit_group;");
            asm volatile("cp.async.wait_group 1;");
        } else {
            asm volatile("cp.async.wait_group 0;");
        }
        __syncthreads();

#pragma unroll
        for (int ks = 0; ks < 2; ks++) {
            int kk = ks * 16;
            uint32_t afr[2][4];
#pragma unroll
            for (int mi = 0; mi < 2; mi++)
                ldsm4(afr[mi], smem_u32(
                    &As[buf][warp * 32 + mi * 16 + (lane & 15)][kk + ((lane & 16) >> 1)]));
            uint32_t bfr[8][2];
#pragma unroll
            for (int p = 0; p < 4; p++) {
                uint32_t t4[4];
                ldsm4(t4, smem_u32(
                    &Bs[buf][p * 16 + ((lane & 16) >> 1) + (lane & 7)][kk + (lane & 8)]));
                bfr[2*p  ][0] = t4[0]; bfr[2*p  ][1] = t4[1];
                bfr[2*p+1][0] = t4[2]; bfr[2*p+1][1] = t4[3];
            }
#pragma unroll
            for (int mi = 0; mi < 2; mi++)
#pragma unroll
                for (int nj = 0; nj < 8; nj++)
                    mma16816(acc[mi][nj], afr[mi], bfr[nj]);
        }
        __syncthreads();
    }

    // Epilogue
    int g = lane >> 2, t2 = (lane & 3) * 2;
#pragma unroll
    for (int mi = 0; mi < 2; mi++)
#pragma unroll
        for (int nj = 0; nj < 8; nj++)
#pragma unroll
            for (int e = 0; e < 4; e++) {
                int m = m0 + warp * 32 + mi * 16 + g + (e >> 1) * 8;
                int n = n0 + nj * 8 + t2 + (e & 1);
                float val = acc[mi][nj][e] + bias[n];
                if (MODE == 0) {
                    int s   = n / 192;
                    int rem = n - s * 192;
                    int nh  = rem >> 5, d = rem & 31;
                    int w = m >> 6, t = m & 63;
                    size_t wh = (size_t)(w * NHH + nh);
                    if (s == 0)      g_qb[(wh * NT + t) * HDD + d] = __float2bfloat16(val * SCALE_F);
                    else if (s == 1) g_kb[(wh * NT + t) * HDD + d] = __float2bfloat16(val);
                    else             g_vt[(wh * HDD + d) * NT + t] = __float2bfloat16(val);
                } else if (MODE == 1) {
                    val = val > 0.f ? val : 0.2f * val;
                    g_h1[(size_t)m * NDIM + n] = __float2bfloat16(val);
                } else if (MODE == 2) {
                    size_t o = (size_t)m * NDIM + n;
                    Cext[o] = g_xmid[o] + val;
                } else {
                    int w = m >> 6, t = m & 63;
                    int bb = w >> 8, wi = w & 255;
                    int wy = wi >> 4, wx = wi & 15;
                    int ty2 = t >> 3, tx2 = t & 7;
                    int oy = (wy * 8 + ty2 + SH) & 127;
                    int ox = (wx * 8 + tx2 + SH) & 127;
                    size_t orow = ((size_t)bb << 14) + (oy << 7) + ox;
                    size_t o = orow * NDIM + n;
                    g_xmid[o] = Rext[o] + val;
                }
            }
}

// ---------------------------------------------------------------------------
// Tensor-core attention (proven in R8, unchanged)
// ---------------------------------------------------------------------------
__global__ void attn_mma()
{
    int wh = blockIdx.x;
    int w  = wh / NHH;
    int wi = w & 255;
    int wy = wi >> 4, wx = wi & 15;
    int nh = wh - w * NHH;

    __shared__ __align__(16) bf16 Qs[64][40];
    __shared__ __align__(16) bf16 Ks[64][40];
    __shared__ __align__(16) bf16 Vt[32][72];
    __shared__ int lab[64];

    int tid = threadIdx.x, lane = tid & 31, warp = tid >> 5;
    size_t base = (size_t)wh * NT * HDD;

#pragma unroll
    for (int i = 0; i < 2; i++) {
        int idx = tid + i * 128;
        int r = idx >> 2, c8 = (idx & 3) * 8;
        *(uint4*)&Qs[r][c8] = *(const uint4*)&g_qb[base + r * HDD + c8];
        *(uint4*)&Ks[r][c8] = *(const uint4*)&g_kb[base + r * HDD + c8];
        int rv = idx >> 3, cv = (idx & 7) * 8;
        *(uint4*)&Vt[rv][cv] = *(const uint4*)&g_vt[base + rv * NT + cv];
    }
    if (tid < 64) {
        int ty = tid >> 3, tx = tid & 7;
        int y = wy * 8 + ty, x = wx * 8 + tx;
        int ry = (y < HH - WS) ? 0 : ((y < HH - SH) ? 1 : 2);
        int rx = (x < WW - WS) ? 0 : ((x < WW - SH) ? 1 : 2);
        lab[tid] = ry * 3 + rx;
    }
    __syncthreads();

    int mrow = warp * 16;

    uint32_t aq[2][4];
#pragma unroll
    for (int kc = 0; kc < 2; kc++)
        ldsm4(aq[kc], smem_u32(
            &Qs[mrow + (lane & 15)][kc * 16 + ((lane & 16) >> 1)]));

    float sacc[8][4] = {};
#pragma unroll
    for (int kc = 0; kc < 2; kc++)
#pragma unroll
        for (int p = 0; p < 4; p++) {
            uint32_t t4[4];
            ldsm4(t4, smem_u32(
                &Ks[p * 16 + ((lane & 16) >> 1) + (lane & 7)][kc * 16 + (lane & 8)]));
            mma16816(sacc[2 * p],     aq[kc], t4);
            mma16816(sacc[2 * p + 1], aq[kc], t4 + 2);
        }

    int g = lane >> 2, tq = lane & 3;
    int r0 = mrow + g, r1 = r0 + 8;
    const float2* b0 = (const float2*)&g_bias[(nh * NT + r0) * NT];
    const float2* b1 = (const float2*)&g_bias[(nh * NT + r1) * NT];
    int l0 = lab[r0], l1 = lab[r1];
    float mx0 = -1e30f, mx1 = -1e30f;
#pragma unroll
    for (int j = 0; j < 8; j++) {
        int c0 = 8 * j + 2 * tq;
        float2 bb0 = b0[4 * j + tq];
        float2 bb1 = b1[4 * j + tq];
        int lc0 = lab[c0], lc1 = lab[c0 + 1];
        sacc[j][0] += bb0.x + (l0 != lc0 ? -100.f : 0.f);
        sacc[j][1] += bb0.y + (l0 != lc1 ? -100.f : 0.f);
        sacc[j][2] += bb1.x + (l1 != lc0 ? -100.f : 0.f);
        sacc[j][3] += bb1.y + (l1 != lc1 ? -100.f : 0.f);
        mx0 = fmaxf(mx0, fmaxf(sacc[j][0], sacc[j][1]));
        mx1 = fmaxf(mx1, fmaxf(sacc[j][2], sacc[j][3]));
    }
    mx0 = fmaxf(mx0, __shfl_xor_sync(0xffffffffu, mx0, 1));
    mx0 = fmaxf(mx0, __shfl_xor_sync(0xffffffffu, mx0, 2));
    mx1 = fmaxf(mx1, __shfl_xor_sync(0xffffffffu, mx1, 1));
    mx1 = fmaxf(mx1, __shfl_xor_sync(0xffffffffu, mx1, 2));
    float s0 = 0.f, s1 = 0.f;
#pragma unroll
    for (int j = 0; j < 8; j++) {
        sacc[j][0] = __expf(sacc[j][0] - mx0);
        sacc[j][1] = __expf(sacc[j][1] - mx0);
        sacc[j][2] = __expf(sacc[j][2] - mx1);
        sacc[j][3] = __expf(sacc[j][3] - mx1);
        s0 += sacc[j][0] + sacc[j][1];
        s1 += sacc[j][2] + sacc[j][3];
    }
    s0 += __shfl_xor_sync(0xffffffffu, s0, 1);
    s0 += __shfl_xor_sync(0xffffffffu, s0, 2);
    s1 += __shfl_xor_sync(0xffffffffu, s1, 1);
    s1 += __shfl_xor_sync(0xffffffffu, s1, 2);
    float inv0 = 1.f / s0, inv1 = 1.f / s1;

    float oacc[4][4] = {};
#pragma unroll
    for (int kc = 0; kc < 4; kc++) {
        uint32_t pa[4];
        pa[0] = packbf(sacc[2*kc  ][0] * inv0, sacc[2*kc  ][1] * inv0);
        pa[1] = packbf(sacc[2*kc  ][2] * inv1, sacc[2*kc  ][3] * inv1);
        pa[2] = packbf(sacc[2*kc+1][0] * inv0, sacc[2*kc+1][1] * inv0);
        pa[3] = packbf(sacc[2*kc+1][2] * inv1, sacc[2*kc+1][3] * inv1);
#pragma unroll
        for (int p = 0; p < 2; p++) {
            uint32_t t4[4];
            ldsm4(t4, smem_u32(
                &Vt[p * 16 + ((lane & 16) >> 1) + (lane & 7)][kc * 16 + (lane & 8)]));
            mma16816(oacc[2 * p],     pa, t4);
            mma16816(oacc[2 * p + 1], pa, t4 + 2);
        }
    }

#pragma unroll
    for (int nj = 0; nj < 4; nj++) {
        int d = nh * HDD + 8 * nj + 2 * tq;
        __nv_bfloat162 v0 = __float22bfloat162_rn(make_float2(oacc[nj][0], oacc[nj][1]));
        __nv_bfloat162 v1 = __float22bfloat162_rn(make_float2(oacc[nj][2], oacc[nj][3]));
        *(__nv_bfloat162*)&g_att[(size_t)(w * NT + r0) * CC + d] = v0;
        *(__nv_bfloat162*)&g_att[(size_t)(w * NT + r1) * CC + d] = v1;
    }
}

// ---------------------------------------------------------------------------
// Launch
// ---------------------------------------------------------------------------
extern "C" void kernel_launch(void* const* d_in, const int* in_sizes, int n_in,
                              void* d_out, int out_size)
{
    const float* x       = (const float*)d_in[0];
    const float* norm1_g = (const float*)d_in[1];
    const float* norm1_b = (const float*)d_in[2];
    const float* qkv_w   = (const float*)d_in[3];
    const float* qkv_b   = (const float*)d_in[4];
    const float* proj_w  = (const float*)d_in[5];
    const float* proj_b  = (const float*)d_in[6];
    const float* rpb     = (const float*)d_in[7];
    const float* norm2_g = (const float*)d_in[8];
    const float* norm2_b = (const float*)d_in[9];
    const float* fc1_w   = (const float*)d_in[10];
    const float* fc1_b   = (const float*)d_in[11];
    const float* fc2_w   = (const float*)d_in[12];
    const float* fc2_b   = (const float*)d_in[13];
    float* out = (float*)d_out;

    cvt_weights<<<576, 256>>>(qkv_w, proj_w, fc1_w, fc2_w);
    bias_kernel<<<96, 256>>>(rpb);

    ln_kernel<0><<<MROWS / 8, 256>>>(x, norm1_g, norm1_b);

    gemm_mma<0, 192, 576><<<dim3(9, 1024), 128>>>(qkv_b, nullptr, nullptr);

    attn_mma<<<NWIN * NHH, 128>>>();

    gemm_mma<3, 192, 192><<<dim3(3, 1024), 128>>>(proj_b, x, nullptr);

    ln_kernel<1><<<MROWS / 8, 256>>>(nullptr, norm2_g, norm2_b);

    gemm_mma<1, 192, 768><<<dim3(12, 1024), 128>>>(fc1_b, nullptr, nullptr);

    gemm_mma<2, 768, 192><<<dim3(3, 1024), 128>>>(fc2_b, nullptr, out);
}

// round 11
// speedup vs baseline: 4.6196x; 1.0733x over previous
#include <cuda_runtime.h>
#include <cuda_bf16.h>
#include <cstdint>

using bf16 = __nv_bfloat16;

// ---------------------------------------------------------------------------
// Problem constants
// ---------------------------------------------------------------------------
constexpr int HH   = 128;
constexpr int WW   = 128;
constexpr int CC   = 192;
constexpr int NHH  = 6;
constexpr int HDD  = 32;
constexpr int WS   = 8;
constexpr int SH   = 4;
constexpr int NT   = 64;
constexpr int NWIN = 2048;
constexpr int MROWS = 131072;
constexpr float SCALE_F = 0.17677669529663689f;

// ---------------------------------------------------------------------------
// Scratch (device globals, only referenced from device code)
// ---------------------------------------------------------------------------
__device__ bf16  g_hwin[(size_t)MROWS * CC];
__device__ bf16  g_qb[(size_t)NWIN * NHH * NT * HDD];  // q*scale [wh][t][d]
__device__ bf16  g_kb[(size_t)NWIN * NHH * NT * HDD];  // k       [wh][t][d]
__device__ bf16  g_vt[(size_t)NWIN * NHH * NT * HDD];  // v^T     [wh][d][t]
__device__ bf16  g_att[(size_t)MROWS * CC];
__device__ float g_xmid[(size_t)MROWS * CC];
__device__ bf16  g_ln2[(size_t)MROWS * CC];
__device__ bf16  g_h1[(size_t)MROWS * 4 * CC];
__device__ float g_bias[NHH * NT * NT];
__device__ bf16  g_wqkv[576 * 192];
__device__ bf16  g_wproj[192 * 192];
__device__ bf16  g_wfc1[768 * 192];
__device__ bf16  g_wfc2[192 * 768];

// ---------------------------------------------------------------------------
// Helpers
// ---------------------------------------------------------------------------
__device__ __forceinline__ uint32_t smem_u32(const void* p) {
    return (uint32_t)__cvta_generic_to_shared(p);
}
__device__ __forceinline__ void cpasync16(uint32_t s, const void* g) {
    asm volatile("cp.async.cg.shared.global [%0], [%1], 16;" :: "r"(s), "l"(g));
}
__device__ __forceinline__ void ldsm4(uint32_t* r, uint32_t a) {
    asm volatile("ldmatrix.sync.aligned.m8n8.x4.shared.b16 {%0,%1,%2,%3}, [%4];"
        : "=r"(r[0]), "=r"(r[1]), "=r"(r[2]), "=r"(r[3]) : "r"(a));
}
__device__ __forceinline__ void mma16816(float* c, const uint32_t* a, const uint32_t* b) {
    asm volatile("mma.sync.aligned.m16n8k16.row.col.f32.bf16.bf16.f32 "
        "{%0,%1,%2,%3}, {%4,%5,%6,%7}, {%8,%9}, {%0,%1,%2,%3};"
        : "+f"(c[0]), "+f"(c[1]), "+f"(c[2]), "+f"(c[3])
        : "r"(a[0]), "r"(a[1]), "r"(a[2]), "r"(a[3]), "r"(b[0]), "r"(b[1]));
}
__device__ __forceinline__ uint32_t packbf(float a, float b) {
    __nv_bfloat162 h = __float22bfloat162_rn(make_float2(a, b));
    return *(uint32_t*)&h;
}

// ---------------------------------------------------------------------------
// Setup: weight conversion + rel-pos bias table (merged)
// ---------------------------------------------------------------------------
__global__ void setup_kernel(const float* __restrict__ qkv,
                             const float* __restrict__ proj,
                             const float* __restrict__ fc1,
                             const float* __restrict__ fc2,
                             const float* __restrict__ rpb)
{
    int i = blockIdx.x * blockDim.x + threadIdx.x;
    if (i < 576 * 192) g_wqkv[i]  = __float2bfloat16(qkv[i]);
    if (i < 192 * 192) g_wproj[i] = __float2bfloat16(proj[i]);
    if (i < 768 * 192) { g_wfc1[i] = __float2bfloat16(fc1[i]);
                         g_wfc2[i] = __float2bfloat16(fc2[i]); }
    if (i < NHH * NT * NT) {
        int nh = i >> 12, rc = i & 4095, r = rc >> 6, c = rc & 63;
        int dy = (r >> 3) - (c >> 3) + 7;
        int dx = (r & 7) - (c & 7) + 7;
        g_bias[i] = rpb[(dy * 15 + dx) * NHH + nh];
    }
}

// ---------------------------------------------------------------------------
// LayerNorm (proven)
// ---------------------------------------------------------------------------
template<int LMODE>
__global__ void ln_kernel(const float* __restrict__ xin,
                          const float* __restrict__ gam,
                          const float* __restrict__ bet)
{
    int warp = (blockIdx.x * blockDim.x + threadIdx.x) >> 5;
    int lane = threadIdx.x & 31;
    if (warp >= MROWS) return;

    const float* in = (LMODE == 0) ? xin : g_xmid;
    bf16* out       = (LMODE == 0) ? g_hwin : g_ln2;

    int src = warp;
    if (LMODE == 0) {
        int w = warp >> 6, t = warp & 63;
        int bb = w >> 8, wi = w & 255;
        int wy = wi >> 4, wx = wi & 15;
        int ty = t >> 3, tx = t & 7;
        int oy = (wy * 8 + ty + SH) & 127;
        int ox = (wx * 8 + tx + SH) & 127;
        src = (bb << 14) + (oy << 7) + ox;
    }
    const float* row = in + (size_t)src * CC;
    float v[6];
    float s = 0.f, s2 = 0.f;
#pragma unroll
    for (int i = 0; i < 6; i++) {
        v[i] = row[lane + 32 * i];
        s  += v[i];
        s2 += v[i] * v[i];
    }
#pragma unroll
    for (int off = 16; off; off >>= 1) {
        s  += __shfl_xor_sync(0xffffffffu, s,  off);
        s2 += __shfl_xor_sync(0xffffffffu, s2, off);
    }
    float mu  = s * (1.f / CC);
    float var = s2 * (1.f / CC) - mu * mu;
    float inv = rsqrtf(var + 1e-5f);
    bf16* orow = out + (size_t)warp * CC;
#pragma unroll
    for (int i = 0; i < 6; i++) {
        int c = lane + 32 * i;
        orow[c] = __float2bfloat16((v[i] - mu) * inv * gam[c] + bet[c]);
    }
}

// ---------------------------------------------------------------------------
// HMMA GEMM, BK=64, 2-stage cp.async double buffer.
// Block 128x64, 128 threads = 4 warps, each warp a 32x64 tile.
// Per chunk: one barrier-free region of 4 k16 steps (24 ldsm + 64 mma)
// so ptxas can pipeline ldsm under mma.
// MODE 0: A=g_hwin,W=g_wqkv  -> q(scaled)/k/vT scatter (bf16)
// MODE 1: A=g_ln2, W=g_wfc1  -> leaky relu -> g_h1 (bf16)
// MODE 2: A=g_h1,  W=g_wfc2  -> + g_xmid -> Cext (fp32)
// MODE 3: A=g_att, W=g_wproj -> window-reverse scatter, + x -> g_xmid
// ---------------------------------------------------------------------------
template<int MODE, int KDIM, int NDIM>
__global__ void __launch_bounds__(128) gemm_mma(const float* __restrict__ bias,
                                                const float* __restrict__ Rext,
                                                float* __restrict__ Cext)
{
    const bf16* A = (MODE == 0) ? g_hwin : (MODE == 1) ? g_ln2 :
                    (MODE == 2) ? g_h1   : g_att;
    const bf16* W = (MODE == 0) ? g_wqkv : (MODE == 1) ? g_wfc1 :
                    (MODE == 2) ? g_wfc2 : g_wproj;

    __shared__ __align__(16) bf16 As[2][128][72];
    __shared__ __align__(16) bf16 Bs[2][64][72];

    int m0 = blockIdx.y * 128, n0 = blockIdx.x * 64;
    int tid = threadIdx.x, lane = tid & 31, warp = tid >> 5;

    constexpr int NCH = KDIM / 64;

    auto prefetch = [&](int ch, int buf) {
        int kt = ch * 64;
#pragma unroll
        for (int i = 0; i < 8; i++) {
            int idx = tid + i * 128;
            int r = idx >> 3, c8 = (idx & 7) * 8;
            cpasync16(smem_u32(&As[buf][r][c8]),
                      &A[(size_t)(m0 + r) * KDIM + kt + c8]);
        }
#pragma unroll
        for (int i = 0; i < 4; i++) {
            int idx = tid + i * 128;
            int r = idx >> 3, c8 = (idx & 7) * 8;
            cpasync16(smem_u32(&Bs[buf][r][c8]),
                      &W[(size_t)(n0 + r) * KDIM + kt + c8]);
        }
    };

    float acc[2][8][4] = {};

    prefetch(0, 0);
    asm volatile("cp.async.commit_group;");

    for (int ch = 0; ch < NCH; ch++) {
        int buf = ch & 1;
        if (ch + 1 < NCH) {
            prefetch(ch + 1, buf ^ 1);
            asm volatile("cp.async.commit_group;");
            asm volatile("cp.async.wait_group 1;");
        } else {
            asm volatile("cp.async.wait_group 0;");
        }
        __syncthreads();

#pragma unroll
        for (int ks = 0; ks < 4; ks++) {
            int kk = ks * 16;
            uint32_t afr[2][4];
#pragma unroll
            for (int mi = 0; mi < 2; mi++)
                ldsm4(afr[mi], smem_u32(
                    &As[buf][warp * 32 + mi * 16 + (lane & 15)][kk + ((lane & 16) >> 1)]));
            uint32_t bfr[8][2];
#pragma unroll
            for (int p = 0; p < 4; p++) {
                uint32_t t4[4];
                ldsm4(t4, smem_u32(
                    &Bs[buf][p * 16 + ((lane & 16) >> 1) + (lane & 7)][kk + (lane & 8)]));
                bfr[2*p  ][0] = t4[0]; bfr[2*p  ][1] = t4[1];
                bfr[2*p+1][0] = t4[2]; bfr[2*p+1][1] = t4[3];
            }
#pragma unroll
            for (int mi = 0; mi < 2; mi++)
#pragma unroll
                for (int nj = 0; nj < 8; nj++)
                    mma16816(acc[mi][nj], afr[mi], bfr[nj]);
        }
        __syncthreads();
    }

    // Epilogue
    int g = lane >> 2, t2 = (lane & 3) * 2;
#pragma unroll
    for (int mi = 0; mi < 2; mi++)
#pragma unroll
        for (int nj = 0; nj < 8; nj++)
#pragma unroll
            for (int e = 0; e < 4; e++) {
                int m = m0 + warp * 32 + mi * 16 + g + (e >> 1) * 8;
                int n = n0 + nj * 8 + t2 + (e & 1);
                float val = acc[mi][nj][e] + bias[n];
                if (MODE == 0) {
                    int s   = n / 192;
                    int rem = n - s * 192;
                    int nh  = rem >> 5, d = rem & 31;
                    int w = m >> 6, t = m & 63;
                    size_t wh = (size_t)(w * NHH + nh);
                    if (s == 0)      g_qb[(wh * NT + t) * HDD + d] = __float2bfloat16(val * SCALE_F);
                    else if (s == 1) g_kb[(wh * NT + t) * HDD + d] = __float2bfloat16(val);
                    else             g_vt[(wh * HDD + d) * NT + t] = __float2bfloat16(val);
                } else if (MODE == 1) {
                    val = val > 0.f ? val : 0.2f * val;
                    g_h1[(size_t)m * NDIM + n] = __float2bfloat16(val);
                } else if (MODE == 2) {
                    size_t o = (size_t)m * NDIM + n;
                    Cext[o] = g_xmid[o] + val;
                } else {
                    int w = m >> 6, t = m & 63;
                    int bb = w >> 8, wi = w & 255;
                    int wy = wi >> 4, wx = wi & 15;
                    int ty2 = t >> 3, tx2 = t & 7;
                    int oy = (wy * 8 + ty2 + SH) & 127;
                    int ox = (wx * 8 + tx2 + SH) & 127;
                    size_t orow = ((size_t)bb << 14) + (oy << 7) + ox;
                    size_t o = orow * NDIM + n;
                    g_xmid[o] = Rext[o] + val;
                }
            }
}

// ---------------------------------------------------------------------------
// Tensor-core attention (proven in R8, unchanged)
// ---------------------------------------------------------------------------
__global__ void attn_mma()
{
    int wh = blockIdx.x;
    int w  = wh / NHH;
    int wi = w & 255;
    int wy = wi >> 4, wx = wi & 15;
    int nh = wh - w * NHH;

    __shared__ __align__(16) bf16 Qs[64][40];
    __shared__ __align__(16) bf16 Ks[64][40];
    __shared__ __align__(16) bf16 Vt[32][72];
    __shared__ int lab[64];

    int tid = threadIdx.x, lane = tid & 31, warp = tid >> 5;
    size_t base = (size_t)wh * NT * HDD;

#pragma unroll
    for (int i = 0; i < 2; i++) {
        int idx = tid + i * 128;
        int r = idx >> 2, c8 = (idx & 3) * 8;
        *(uint4*)&Qs[r][c8] = *(const uint4*)&g_qb[base + r * HDD + c8];
        *(uint4*)&Ks[r][c8] = *(const uint4*)&g_kb[base + r * HDD + c8];
        int rv = idx >> 3, cv = (idx & 7) * 8;
        *(uint4*)&Vt[rv][cv] = *(const uint4*)&g_vt[base + rv * NT + cv];
    }
    if (tid < 64) {
        int ty = tid >> 3, tx = tid & 7;
        int y = wy * 8 + ty, x = wx * 8 + tx;
        int ry = (y < HH - WS) ? 0 : ((y < HH - SH) ? 1 : 2);
        int rx = (x < WW - WS) ? 0 : ((x < WW - SH) ? 1 : 2);
        lab[tid] = ry * 3 + rx;
    }
    __syncthreads();

    int mrow = warp * 16;

    uint32_t aq[2][4];
#pragma unroll
    for (int kc = 0; kc < 2; kc++)
        ldsm4(aq[kc], smem_u32(
            &Qs[mrow + (lane & 15)][kc * 16 + ((lane & 16) >> 1)]));

    float sacc[8][4] = {};
#pragma unroll
    for (int kc = 0; kc < 2; kc++)
#pragma unroll
        for (int p = 0; p < 4; p++) {
            uint32_t t4[4];
            ldsm4(t4, smem_u32(
                &Ks[p * 16 + ((lane & 16) >> 1) + (lane & 7)][kc * 16 + (lane & 8)]));
            mma16816(sacc[2 * p],     aq[kc], t4);
            mma16816(sacc[2 * p + 1], aq[kc], t4 + 2);
        }

    int g = lane >> 2, tq = lane & 3;
    int r0 = mrow + g, r1 = r0 + 8;
    const float2* b0 = (const float2*)&g_bias[(nh * NT + r0) * NT];
    const float2* b1 = (const float2*)&g_bias[(nh * NT + r1) * NT];
    int l0 = lab[r0], l1 = lab[r1];
    float mx0 = -1e30f, mx1 = -1e30f;
#pragma unroll
    for (int j = 0; j < 8; j++) {
        int c0 = 8 * j + 2 * tq;
        float2 bb0 = b0[4 * j + tq];
        float2 bb1 = b1[4 * j + tq];
        int lc0 = lab[c0], lc1 = lab[c0 + 1];
        sacc[j][0] += bb0.x + (l0 != lc0 ? -100.f : 0.f);
        sacc[j][1] += bb0.y + (l0 != lc1 ? -100.f : 0.f);
        sacc[j][2] += bb1.x + (l1 != lc0 ? -100.f : 0.f);
        sacc[j][3] += bb1.y + (l1 != lc1 ? -100.f : 0.f);
        mx0 = fmaxf(mx0, fmaxf(sacc[j][0], sacc[j][1]));
        mx1 = fmaxf(mx1, fmaxf(sacc[j][2], sacc[j][3]));
    }
    mx0 = fmaxf(mx0, __shfl_xor_sync(0xffffffffu, mx0, 1));
    mx0 = fmaxf(mx0, __shfl_xor_sync(0xffffffffu, mx0, 2));
    mx1 = fmaxf(mx1, __shfl_xor_sync(0xffffffffu, mx1, 1));
    mx1 = fmaxf(mx1, __shfl_xor_sync(0xffffffffu, mx1, 2));
    float s0 = 0.f, s1 = 0.f;
#pragma unroll
    for (int j = 0; j < 8; j++) {
        sacc[j][0] = __expf(sacc[j][0] - mx0);
        sacc[j][1] = __expf(sacc[j][1] - mx0);
        sacc[j][2] = __expf(sacc[j][2] - mx1);
        sacc[j][3] = __expf(sacc[j][3] - mx1);
        s0 += sacc[j][0] + sacc[j][1];
        s1 += sacc[j][2] + sacc[j][3];
    }
    s0 += __shfl_xor_sync(0xffffffffu, s0, 1);
    s0 += __shfl_xor_sync(0xffffffffu, s0, 2);
    s1 += __shfl_xor_sync(0xffffffffu, s1, 1);
    s1 += __shfl_xor_sync(0xffffffffu, s1, 2);
    float inv0 = 1.f / s0, inv1 = 1.f / s1;

    float oacc[4][4] = {};
#pragma unroll
    for (int kc = 0; kc < 4; kc++) {
        uint32_t pa[4];
        pa[0] = packbf(sacc[2*kc  ][0] * inv0, sacc[2*kc  ][1] * inv0);
        pa[1] = packbf(sacc[2*kc  ][2] * inv1, sacc[2*kc  ][3] * inv1);
        pa[2] = packbf(sacc[2*kc+1][0] * inv0, sacc[2*kc+1][1] * inv0);
        pa[3] = packbf(sacc[2*kc+1][2] * inv1, sacc[2*kc+1][3] * inv1);
#pragma unroll
        for (int p = 0; p < 2; p++) {
            uint32_t t4[4];
            ldsm4(t4, smem_u32(
                &Vt[p * 16 + ((lane & 16) >> 1) + (lane & 7)][kc * 16 + (lane & 8)]));
            mma16816(oacc[2 * p],     pa, t4);
            mma16816(oacc[2 * p + 1], pa, t4 + 2);
        }
    }

#pragma unroll
    for (int nj = 0; nj < 4; nj++) {
        int d = nh * HDD + 8 * nj + 2 * tq;
        __nv_bfloat162 v0 = __float22bfloat162_rn(make_float2(oacc[nj][0], oacc[nj][1]));
        __nv_bfloat162 v1 = __float22bfloat162_rn(make_float2(oacc[nj][2], oacc[nj][3]));
        *(__nv_bfloat162*)&g_att[(size_t)(w * NT + r0) * CC + d] = v0;
        *(__nv_bfloat162*)&g_att[(size_t)(w * NT + r1) * CC + d] = v1;
    }
}

// ---------------------------------------------------------------------------
// Launch
// ---------------------------------------------------------------------------
extern "C" void kernel_launch(void* const* d_in, const int* in_sizes, int n_in,
                              void* d_out, int out_size)
{
    const float* x       = (const float*)d_in[0];
    const float* norm1_g = (const float*)d_in[1];
    const float* norm1_b = (const float*)d_in[2];
    const float* qkv_w   = (const float*)d_in[3];
    const float* qkv_b   = (const float*)d_in[4];
    const float* proj_w  = (const float*)d_in[5];
    const float* proj_b  = (const float*)d_in[6];
    const float* rpb     = (const float*)d_in[7];
    const float* norm2_g = (const float*)d_in[8];
    const float* norm2_b = (const float*)d_in[9];
    const float* fc1_w   = (const float*)d_in[10];
    const float* fc1_b   = (const float*)d_in[11];
    const float* fc2_w   = (const float*)d_in[12];
    const float* fc2_b   = (const float*)d_in[13];
    float* out = (float*)d_out;

    setup_kernel<<<576, 256>>>(qkv_w, proj_w, fc1_w, fc2_w, rpb);

    ln_kernel<0><<<MROWS / 8, 256>>>(x, norm1_g, norm1_b);

    gemm_mma<0, 192, 576><<<dim3(9, 1024), 128>>>(qkv_b, nullptr, nullptr);

    attn_mma<<<NWIN * NHH, 128>>>();

    gemm_mma<3, 192, 192><<<dim3(3, 1024), 128>>>(proj_b, x, nullptr);

    ln_kernel<1><<<MROWS / 8, 256>>>(nullptr, norm2_g, norm2_b);

    gemm_mma<1, 192, 768><<<dim3(12, 1024), 128>>>(fc1_b, nullptr, nullptr);

    gemm_mma<2, 768, 192><<<dim3(3, 1024), 128>>>(fc2_b, nullptr, out);
}

// round 12
// speedup vs baseline: 6.6283x; 1.4348x over previous
#include <cuda_runtime.h>
#include <cuda_bf16.h>
#include <cstdint>

using bf16 = __nv_bfloat16;

// ---------------------------------------------------------------------------
// Problem constants
// ---------------------------------------------------------------------------
constexpr int HH   = 128;
constexpr int WW   = 128;
constexpr int CC   = 192;
constexpr int NHH  = 6;
constexpr int HDD  = 32;
constexpr int WS   = 8;
constexpr int SH   = 4;
constexpr int NT   = 64;
constexpr int NWIN = 2048;
constexpr int MROWS = 131072;
constexpr float SCALE_F = 0.17677669529663689f;

// ---------------------------------------------------------------------------
// Scratch (device globals, only referenced from device code)
// ---------------------------------------------------------------------------
__device__ bf16  g_hwin[(size_t)MROWS * CC];
__device__ bf16  g_qb[(size_t)NWIN * NHH * NT * HDD];  // q*scale [wh][t][d]
__device__ bf16  g_kb[(size_t)NWIN * NHH * NT * HDD];  // k       [wh][t][d]
__device__ bf16  g_vt[(size_t)NWIN * NHH * NT * HDD];  // v^T     [wh][d][t]
__device__ bf16  g_att[(size_t)MROWS * CC];
__device__ float g_xmid[(size_t)MROWS * CC];
__device__ bf16  g_ln2[(size_t)MROWS * CC];
__device__ bf16  g_h1[(size_t)MROWS * 4 * CC];
__device__ float g_bias[NHH * NT * NT];
__device__ bf16  g_wqkv[576 * 192];
__device__ bf16  g_wproj[192 * 192];
__device__ bf16  g_wfc1[768 * 192];
__device__ bf16  g_wfc2[192 * 768];

// ---------------------------------------------------------------------------
// Helpers
// ---------------------------------------------------------------------------
__device__ __forceinline__ uint32_t smem_u32(const void* p) {
    return (uint32_t)__cvta_generic_to_shared(p);
}
__device__ __forceinline__ void cpasync16(uint32_t s, const void* g) {
    asm volatile("cp.async.cg.shared.global [%0], [%1], 16;" :: "r"(s), "l"(g));
}
__device__ __forceinline__ void ldsm4(uint32_t* r, uint32_t a) {
    asm volatile("ldmatrix.sync.aligned.m8n8.x4.shared.b16 {%0,%1,%2,%3}, [%4];"
        : "=r"(r[0]), "=r"(r[1]), "=r"(r[2]), "=r"(r[3]) : "r"(a));
}
__device__ __forceinline__ void mma16816(float* c, const uint32_t* a, const uint32_t* b) {
    asm volatile("mma.sync.aligned.m16n8k16.row.col.f32.bf16.bf16.f32 "
        "{%0,%1,%2,%3}, {%4,%5,%6,%7}, {%8,%9}, {%0,%1,%2,%3};"
        : "+f"(c[0]), "+f"(c[1]), "+f"(c[2]), "+f"(c[3])
        : "r"(a[0]), "r"(a[1]), "r"(a[2]), "r"(a[3]), "r"(b[0]), "r"(b[1]));
}
__device__ __forceinline__ uint32_t packbf(float a, float b) {
    __nv_bfloat162 h = __float22bfloat162_rn(make_float2(a, b));
    return *(uint32_t*)&h;
}

// ---------------------------------------------------------------------------
// Setup: weight conversion + rel-pos bias table (merged)
// ---------------------------------------------------------------------------
__global__ void setup_kernel(const float* __restrict__ qkv,
                             const float* __restrict__ proj,
                             const float* __restrict__ fc1,
                             const float* __restrict__ fc2,
                             const float* __restrict__ rpb)
{
    int i = blockIdx.x * blockDim.x + threadIdx.x;
    if (i < 576 * 192) g_wqkv[i]  = __float2bfloat16(qkv[i]);
    if (i < 192 * 192) g_wproj[i] = __float2bfloat16(proj[i]);
    if (i < 768 * 192) { g_wfc1[i] = __float2bfloat16(fc1[i]);
                         g_wfc2[i] = __float2bfloat16(fc2[i]); }
    if (i < NHH * NT * NT) {
        int nh = i >> 12, rc = i & 4095, r = rc >> 6, c = rc & 63;
        int dy = (r >> 3) - (c >> 3) + 7;
        int dx = (r & 7) - (c & 7) + 7;
        g_bias[i] = rpb[(dy * 15 + dx) * NHH + nh];
    }
}

// ---------------------------------------------------------------------------
// LayerNorm (proven)
// ---------------------------------------------------------------------------
template<int LMODE>
__global__ void ln_kernel(const float* __restrict__ xin,
                          const float* __restrict__ gam,
                          const float* __restrict__ bet)
{
    int warp = (blockIdx.x * blockDim.x + threadIdx.x) >> 5;
    int lane = threadIdx.x & 31;
    if (warp >= MROWS) return;

    const float* in = (LMODE == 0) ? xin : g_xmid;
    bf16* out       = (LMODE == 0) ? g_hwin : g_ln2;

    int src = warp;
    if (LMODE == 0) {
        int w = warp >> 6, t = warp & 63;
        int bb = w >> 8, wi = w & 255;
        int wy = wi >> 4, wx = wi & 15;
        int ty = t >> 3, tx = t & 7;
        int oy = (wy * 8 + ty + SH) & 127;
        int ox = (wx * 8 + tx + SH) & 127;
        src = (bb << 14) + (oy << 7) + ox;
    }
    const float* row = in + (size_t)src * CC;
    float v[6];
    float s = 0.f, s2 = 0.f;
#pragma unroll
    for (int i = 0; i < 6; i++) {
        v[i] = row[lane + 32 * i];
        s  += v[i];
        s2 += v[i] * v[i];
    }
#pragma unroll
    for (int off = 16; off; off >>= 1) {
        s  += __shfl_xor_sync(0xffffffffu, s,  off);
        s2 += __shfl_xor_sync(0xffffffffu, s2, off);
    }
    float mu  = s * (1.f / CC);
    float var = s2 * (1.f / CC) - mu * mu;
    float inv = rsqrtf(var + 1e-5f);
    bf16* orow = out + (size_t)warp * CC;
#pragma unroll
    for (int i = 0; i < 6; i++) {
        int c = lane + 32 * i;
        orow[c] = __float2bfloat16((v[i] - mu) * inv * gam[c] + bet[c]);
    }
}

// ---------------------------------------------------------------------------
// HMMA GEMM, BK=64, 2-stage cp.async smem pipeline + 2-deep register
// fragment pipeline (ldsm for ks+1 issued before mma of ks), vectorized
// epilogue stores.
// Block 128x64, 128 threads = 4 warps, each warp a 32x64 tile.
// MODE 0: A=g_hwin,W=g_wqkv  -> q(scaled)/k/vT scatter (bf16)
// MODE 1: A=g_ln2, W=g_wfc1  -> leaky relu -> g_h1 (bf16)
// MODE 2: A=g_h1,  W=g_wfc2  -> + g_xmid -> Cext (fp32)
// MODE 3: A=g_att, W=g_wproj -> window-reverse scatter, + x -> g_xmid
// ---------------------------------------------------------------------------
template<int MODE, int KDIM, int NDIM>
__global__ void __launch_bounds__(128) gemm_mma(const float* __restrict__ bias,
                                                const float* __restrict__ Rext,
                                                float* __restrict__ Cext)
{
    const bf16* A = (MODE == 0) ? g_hwin : (MODE == 1) ? g_ln2 :
                    (MODE == 2) ? g_h1   : g_att;
    const bf16* W = (MODE == 0) ? g_wqkv : (MODE == 1) ? g_wfc1 :
                    (MODE == 2) ? g_wfc2 : g_wproj;

    __shared__ __align__(16) bf16 As[2][128][72];
    __shared__ __align__(16) bf16 Bs[2][64][72];

    int m0 = blockIdx.y * 128, n0 = blockIdx.x * 64;
    int tid = threadIdx.x, lane = tid & 31, warp = tid >> 5;

    constexpr int NCH = KDIM / 64;

    auto prefetch = [&](int ch, int buf) {
        int kt = ch * 64;
#pragma unroll
        for (int i = 0; i < 8; i++) {
            int idx = tid + i * 128;
            int r = idx >> 3, c8 = (idx & 7) * 8;
            cpasync16(smem_u32(&As[buf][r][c8]),
                      &A[(size_t)(m0 + r) * KDIM + kt + c8]);
        }
#pragma unroll
        for (int i = 0; i < 4; i++) {
            int idx = tid + i * 128;
            int r = idx >> 3, c8 = (idx & 7) * 8;
            cpasync16(smem_u32(&Bs[buf][r][c8]),
                      &W[(size_t)(n0 + r) * KDIM + kt + c8]);
        }
    };

    float acc[2][8][4] = {};

    prefetch(0, 0);
    asm volatile("cp.async.commit_group;");

    // fragment double buffers
    uint32_t afr[2][2][4];
    uint32_t bfr[2][8][2];

    for (int ch = 0; ch < NCH; ch++) {
        int buf = ch & 1;
        if (ch + 1 < NCH) {
            prefetch(ch + 1, buf ^ 1);
            asm volatile("cp.async.commit_group;");
            asm volatile("cp.async.wait_group 1;");
        } else {
            asm volatile("cp.async.wait_group 0;");
        }
        __syncthreads();

        // load frags for ks=0
        {
#pragma unroll
            for (int mi = 0; mi < 2; mi++)
                ldsm4(afr[0][mi], smem_u32(
                    &As[buf][warp * 32 + mi * 16 + (lane & 15)][((lane & 16) >> 1)]));
#pragma unroll
            for (int p = 0; p < 4; p++) {
                uint32_t t4[4];
                ldsm4(t4, smem_u32(
                    &Bs[buf][p * 16 + ((lane & 16) >> 1) + (lane & 7)][(lane & 8)]));
                bfr[0][2*p  ][0] = t4[0]; bfr[0][2*p  ][1] = t4[1];
                bfr[0][2*p+1][0] = t4[2]; bfr[0][2*p+1][1] = t4[3];
            }
        }

#pragma unroll
        for (int ks = 0; ks < 4; ks++) {
            int cur = ks & 1, nxt = cur ^ 1;
            if (ks < 3) {
                int kk = (ks + 1) * 16;
#pragma unroll
                for (int mi = 0; mi < 2; mi++)
                    ldsm4(afr[nxt][mi], smem_u32(
                        &As[buf][warp * 32 + mi * 16 + (lane & 15)][kk + ((lane & 16) >> 1)]));
#pragma unroll
                for (int p = 0; p < 4; p++) {
                    uint32_t t4[4];
                    ldsm4(t4, smem_u32(
                        &Bs[buf][p * 16 + ((lane & 16) >> 1) + (lane & 7)][kk + (lane & 8)]));
                    bfr[nxt][2*p  ][0] = t4[0]; bfr[nxt][2*p  ][1] = t4[1];
                    bfr[nxt][2*p+1][0] = t4[2]; bfr[nxt][2*p+1][1] = t4[3];
                }
            }
#pragma unroll
            for (int mi = 0; mi < 2; mi++)
#pragma unroll
                for (int nj = 0; nj < 8; nj++)
                    mma16816(acc[mi][nj], afr[cur][mi], bfr[cur][nj]);
        }
        __syncthreads();
    }

    // ------------------------------------------------------------------
    // Epilogue, vectorized: acc pairs (c[2h],c[2h+1]) are (m,n),(m,n+1).
    // ------------------------------------------------------------------
    int g = lane >> 2, t2 = (lane & 3) * 2;
#pragma unroll
    for (int nj = 0; nj < 8; nj++) {
        int n = n0 + nj * 8 + t2;
        float2 bv = *(const float2*)&bias[n];
#pragma unroll
        for (int mi = 0; mi < 2; mi++)
#pragma unroll
            for (int h = 0; h < 2; h++) {
                int m = m0 + warp * 32 + mi * 16 + g + h * 8;
                float v0 = acc[mi][nj][2 * h]     + bv.x;
                float v1 = acc[mi][nj][2 * h + 1] + bv.y;
                if (MODE == 0) {
                    int s   = n / 192;
                    int rem = n - s * 192;
                    int nh  = rem >> 5, d = rem & 31;
                    int w = m >> 6, t = m & 63;
                    size_t wh = (size_t)(w * NHH + nh);
                    if (s == 0) {
                        *(__nv_bfloat162*)&g_qb[(wh * NT + t) * HDD + d] =
                            __float22bfloat162_rn(make_float2(v0 * SCALE_F, v1 * SCALE_F));
                    } else if (s == 1) {
                        *(__nv_bfloat162*)&g_kb[(wh * NT + t) * HDD + d] =
                            __float22bfloat162_rn(make_float2(v0, v1));
                    } else {
                        g_vt[(wh * HDD + d)     * NT + t] = __float2bfloat16(v0);
                        g_vt[(wh * HDD + d + 1) * NT + t] = __float2bfloat16(v1);
                    }
                } else if (MODE == 1) {
                    v0 = v0 > 0.f ? v0 : 0.2f * v0;
                    v1 = v1 > 0.f ? v1 : 0.2f * v1;
                    *(__nv_bfloat162*)&g_h1[(size_t)m * NDIM + n] =
                        __float22bfloat162_rn(make_float2(v0, v1));
                } else if (MODE == 2) {
                    size_t o = (size_t)m * NDIM + n;
                    float2 r2 = *(const float2*)&g_xmid[o];
                    *(float2*)&Cext[o] = make_float2(r2.x + v0, r2.y + v1);
                } else {
                    int w = m >> 6, t = m & 63;
                    int bb = w >> 8, wi = w & 255;
                    int wy = wi >> 4, wx = wi & 15;
                    int ty2 = t >> 3, tx2 = t & 7;
                    int oy = (wy * 8 + ty2 + SH) & 127;
                    int ox = (wx * 8 + tx2 + SH) & 127;
                    size_t orow = ((size_t)bb << 14) + (oy << 7) + ox;
                    size_t o = orow * NDIM + n;
                    float2 r2 = *(const float2*)&Rext[o];
                    *(float2*)&g_xmid[o] = make_float2(r2.x + v0, r2.y + v1);
                }
            }
    }
}

// ---------------------------------------------------------------------------
// Tensor-core attention (proven in R8, unchanged)
// ---------------------------------------------------------------------------
__global__ void attn_mma()
{
    int wh = blockIdx.x;
    int w  = wh / NHH;
    int wi = w & 255;
    int wy = wi >> 4, wx = wi & 15;
    int nh = wh - w * NHH;

    __shared__ __align__(16) bf16 Qs[64][40];
    __shared__ __align__(16) bf16 Ks[64][40];
    __shared__ __align__(16) bf16 Vt[32][72];
    __shared__ int lab[64];

    int tid = threadIdx.x, lane = tid & 31, warp = tid >> 5;
    size_t base = (size_t)wh * NT * HDD;

#pragma unroll
    for (int i = 0; i < 2; i++) {
        int idx = tid + i * 128;
        int r = idx >> 2, c8 = (idx & 3) * 8;
        *(uint4*)&Qs[r][c8] = *(const uint4*)&g_qb[base + r * HDD + c8];
        *(uint4*)&Ks[r][c8] = *(const uint4*)&g_kb[base + r * HDD + c8];
        int rv = idx >> 3, cv = (idx & 7) * 8;
        *(uint4*)&Vt[rv][cv] = *(const uint4*)&g_vt[base + rv * NT + cv];
    }
    if (tid < 64) {
        int ty = tid >> 3, tx = tid & 7;
        int y = wy * 8 + ty, x = wx * 8 + tx;
        int ry = (y < HH - WS) ? 0 : ((y < HH - SH) ? 1 : 2);
        int rx = (x < WW - WS) ? 0 : ((x < WW - SH) ? 1 : 2);
        lab[tid] = ry * 3 + rx;
    }
    __syncthreads();

    int mrow = warp * 16;

    uint32_t aq[2][4];
#pragma unroll
    for (int kc = 0; kc < 2; kc++)
        ldsm4(aq[kc], smem_u32(
            &Qs[mrow + (lane & 15)][kc * 16 + ((lane & 16) >> 1)]));

    float sacc[8][4] = {};
#pragma unroll
    for (int kc = 0; kc < 2; kc++)
#pragma unroll
        for (int p = 0; p < 4; p++) {
            uint32_t t4[4];
            ldsm4(t4, smem_u32(
                &Ks[p * 16 + ((lane & 16) >> 1) + (lane & 7)][kc * 16 + (lane & 8)]));
            mma16816(sacc[2 * p],     aq[kc], t4);
            mma16816(sacc[2 * p + 1], aq[kc], t4 + 2);
        }

    int g = lane >> 2, tq = lane & 3;
    int r0 = mrow + g, r1 = r0 + 8;
    const float2* b0 = (const float2*)&g_bias[(nh * NT + r0) * NT];
    const float2* b1 = (const float2*)&g_bias[(nh * NT + r1) * NT];
    int l0 = lab[r0], l1 = lab[r1];
    float mx0 = -1e30f, mx1 = -1e30f;
#pragma unroll
    for (int j = 0; j < 8; j++) {
        int c0 = 8 * j + 2 * tq;
        float2 bb0 = b0[4 * j + tq];
        float2 bb1 = b1[4 * j + tq];
        int lc0 = lab[c0], lc1 = lab[c0 + 1];
        sacc[j][0] += bb0.x + (l0 != lc0 ? -100.f : 0.f);
        sacc[j][1] += bb0.y + (l0 != lc1 ? -100.f : 0.f);
        sacc[j][2] += bb1.x + (l1 != lc0 ? -100.f : 0.f);
        sacc[j][3] += bb1.y + (l1 != lc1 ? -100.f : 0.f);
        mx0 = fmaxf(mx0, fmaxf(sacc[j][0], sacc[j][1]));
        mx1 = fmaxf(mx1, fmaxf(sacc[j][2], sacc[j][3]));
    }
    mx0 = fmaxf(mx0, __shfl_xor_sync(0xffffffffu, mx0, 1));
    mx0 = fmaxf(mx0, __shfl_xor_sync(0xffffffffu, mx0, 2));
    mx1 = fmaxf(mx1, __shfl_xor_sync(0xffffffffu, mx1, 1));
    mx1 = fmaxf(mx1, __shfl_xor_sync(0xffffffffu, mx1, 2));
    float s0 = 0.f, s1 = 0.f;
#pragma unroll
    for (int j = 0; j < 8; j++) {
        sacc[j][0] = __expf(sacc[j][0] - mx0);
        sacc[j][1] = __expf(sacc[j][1] - mx0);
        sacc[j][2] = __expf(sacc[j][2] - mx1);
        sacc[j][3] = __expf(sacc[j][3] - mx1);
        s0 += sacc[j][0] + sacc[j][1];
        s1 += sacc[j][2] + sacc[j][3];
    }
    s0 += __shfl_xor_sync(0xffffffffu, s0, 1);
    s0 += __shfl_xor_sync(0xffffffffu, s0, 2);
    s1 += __shfl_xor_sync(0xffffffffu, s1, 1);
    s1 += __shfl_xor_sync(0xffffffffu, s1, 2);
    float inv0 = 1.f / s0, inv1 = 1.f / s1;

    float oacc[4][4] = {};
#pragma unroll
    for (int kc = 0; kc < 4; kc++) {
        uint32_t pa[4];
        pa[0] = packbf(sacc[2*kc  ][0] * inv0, sacc[2*kc  ][1] * inv0);
        pa[1] = packbf(sacc[2*kc  ][2] * inv1, sacc[2*kc  ][3] * inv1);
        pa[2] = packbf(sacc[2*kc+1][0] * inv0, sacc[2*kc+1][1] * inv0);
        pa[3] = packbf(sacc[2*kc+1][2] * inv1, sacc[2*kc+1][3] * inv1);
#pragma unroll
        for (int p = 0; p < 2; p++) {
            uint32_t t4[4];
            ldsm4(t4, smem_u32(
                &Vt[p * 16 + ((lane & 16) >> 1) + (lane & 7)][kc * 16 + (lane & 8)]));
            mma16816(oacc[2 * p],     pa, t4);
            mma16816(oacc[2 * p + 1], pa, t4 + 2);
        }
    }

#pragma unroll
    for (int nj = 0; nj < 4; nj++) {
        int d = nh * HDD + 8 * nj + 2 * tq;
        __nv_bfloat162 v0 = __float22bfloat162_rn(make_float2(oacc[nj][0], oacc[nj][1]));
        __nv_bfloat162 v1 = __float22bfloat162_rn(make_float2(oacc[nj][2], oacc[nj][3]));
        *(__nv_bfloat162*)&g_att[(size_t)(w * NT + r0) * CC + d] = v0;
        *(__nv_bfloat162*)&g_att[(size_t)(w * NT + r1) * CC + d] = v1;
    }
}

// ---------------------------------------------------------------------------
// Launch
// ---------------------------------------------------------------------------
extern "C" void kernel_launch(void* const* d_in, const int* in_sizes, int n_in,
                              void* d_out, int out_size)
{
    const float* x       = (const float*)d_in[0];
    const float* norm1_g = (const float*)d_in[1];
    const float* norm1_b = (const float*)d_in[2];
    const float* qkv_w   = (const float*)d_in[3];
    const float* qkv_b   = (const float*)d_in[4];
    const float* proj_w  = (const float*)d_in[5];
    const float* proj_b  = (const float*)d_in[6];
    const float* rpb     = (const float*)d_in[7];
    const float* norm2_g = (const float*)d_in[8];
    const float* norm2_b = (const float*)d_in[9];
    const float* fc1_w   = (const float*)d_in[10];
    const float* fc1_b   = (const float*)d_in[11];
    const float* fc2_w   = (const float*)d_in[12];
    const float* fc2_b   = (const float*)d_in[13];
    float* out = (float*)d_out;

    setup_kernel<<<576, 256>>>(qkv_w, proj_w, fc1_w, fc2_w, rpb);

    ln_kernel<0><<<MROWS / 8, 256>>>(x, norm1_g, norm1_b);

    gemm_mma<0, 192, 576><<<dim3(9, 1024), 128>>>(qkv_b, nullptr, nullptr);

    attn_mma<<<NWIN * NHH, 128>>>();

    gemm_mma<3, 192, 192><<<dim3(3, 1024), 128>>>(proj_b, x, nullptr);

    ln_kernel<1><<<MROWS / 8, 256>>>(nullptr, norm2_g, norm2_b);

    gemm_mma<1, 192, 768><<<dim3(12, 1024), 128>>>(fc1_b, nullptr, nullptr);

    gemm_mma<2, 768, 192><<<dim3(3, 1024), 128>>>(fc2_b, nullptr, out);
}